// round 2
// baseline (speedup 1.0000x reference)
#include <cuda_runtime.h>
#include <cuda_bf16.h>
#include <cstddef>

// ---------------- problem constants ----------------
#define CAMS 6
#define HEADS 8
#define PTS 2
#define LAYERS 3
#define D 256
#define DH 32
#define FFN 512
#define VZ 8
#define VH 50
#define VW 50
#define NQ (VZ*VH*VW)          // 20000
#define IN_C 768
#define FH 8
#define FW 22
#define L 176                   // FH*FW
#define LVIS 44

#define X1_C 256
#define SX 100
#define SY 100
#define SZ 16
#define SPAT ((size_t)SX*SY*SZ)   // 160000
#define OC3 192

#define XOUT_SZ ((size_t)OC3*SPAT)          // 30,720,000
#define CAMX_SZ ((size_t)CAMS*IN_C*L)       // 811,008

// ---------------- scratch (static device globals; no allocation) ----------------
__device__ float g_full[CAMS*L*IN_C];
__device__ float g_feat[CAMS*L*D];
__device__ float g_val [CAMS*L*D];
__device__ float g_off [NQ*HEADS*CAMS*PTS*2];
__device__ float g_att [NQ*HEADS*CAMS*PTS];
__device__ float g_agg [NQ*D];
__device__ float g_q   [NQ*D];
__device__ float g_qt  [NQ*D];
__device__ float g_h1  [NQ*FFN];
__device__ float g_wdt [8*D*D];
__device__ float g_x1  [(size_t)X1_C*SX*SY*SZ];   // 40.96M floats
__device__ double g_gnsum[32];
__device__ float  g_gnmi[32];

// ---------------- restore tokens + write cam_x output ----------------
__global__ void k_restore(const float* __restrict__ camx,
                          const int* __restrict__ ids,
                          const float* __restrict__ mask_tok,
                          float* __restrict__ full,
                          float* __restrict__ camx_out)
{
    int tok = blockIdx.x;            // 0..1055
    int n = tok / L, p = tok % L;
    int t = ids[n*L + p];
    for (int c = threadIdx.x; c < IN_C; c += blockDim.x) {
        float v = (t < LVIS) ? camx[((size_t)n*LVIS + t)*IN_C + c] : mask_tok[c];
        full[(size_t)tok*IN_C + c] = v;
        camx_out[((size_t)n*IN_C + c)*L + p] = v;
    }
}

// ---------------- generic tiled SGEMM  C = A(MxK) @ B(KxN), epilogues ----------------
// MODE: 0 none, 1 +bias, 2 relu(+bias), 3 +bias+res, 4 feat, 5 deconv scatter
#define TM 64
#define TN 64
#define TKK 16
template<int MODE, bool TB>
__global__ void gemm_k(const float* __restrict__ A, const float* __restrict__ B,
                       float* __restrict__ C, int M, int N, int K,
                       const float* __restrict__ bias, const float* __restrict__ res,
                       const float* __restrict__ e1, const float* __restrict__ e2,
                       int p1, int p2, int p3)
{
    __shared__ float As[TKK][TM+4];
    __shared__ float Bs[TKK][TN+4];
    int m0 = blockIdx.y * TM, n0 = blockIdx.x * TN;
    int t = threadIdx.x;
    int tx = t & 15, ty = t >> 4;
    float acc[4][4] = {};
    for (int k0 = 0; k0 < K; k0 += TKK) {
        for (int i = t; i < TM*TKK; i += 256) {
            int mm = i >> 4, kk = i & 15;
            int m = m0 + mm, k = k0 + kk;
            As[kk][mm] = (m < M && k < K) ? A[(size_t)m*K + k] : 0.f;
        }
        if (!TB) {
            for (int i = t; i < TKK*TN; i += 256) {
                int kk = i >> 6, nn = i & 63;
                int k = k0 + kk, n = n0 + nn;
                Bs[kk][nn] = (k < K && n < N) ? B[(size_t)k*N + n] : 0.f;
            }
        } else {
            for (int i = t; i < TKK*TN; i += 256) {
                int nn = i >> 4, kk = i & 15;
                int k = k0 + kk, n = n0 + nn;
                Bs[kk][nn] = (k < K && n < N) ? B[(size_t)n*K + k] : 0.f;
            }
        }
        __syncthreads();
        #pragma unroll
        for (int kk = 0; kk < TKK; kk++) {
            float a[4], b[4];
            #pragma unroll
            for (int i = 0; i < 4; i++) a[i] = As[kk][ty*4 + i];
            #pragma unroll
            for (int j = 0; j < 4; j++) b[j] = Bs[kk][tx*4 + j];
            #pragma unroll
            for (int i = 0; i < 4; i++)
                #pragma unroll
                for (int j = 0; j < 4; j++) acc[i][j] += a[i]*b[j];
        }
        __syncthreads();
    }
    #pragma unroll
    for (int i = 0; i < 4; i++) {
        int row = m0 + ty*4 + i;
        if (row >= M) continue;
        #pragma unroll
        for (int j = 0; j < 4; j++) {
            int col = n0 + tx*4 + j;
            if (col >= N) continue;
            float v = acc[i][j];
            if (MODE == 1) v += bias[col];
            else if (MODE == 2) { v += bias[col]; v = v > 0.f ? v : 0.f; }
            else if (MODE == 3) v += bias[col] + res[(size_t)row*N + col];
            else if (MODE == 4) {
                v += bias[col]; v = v > 0.f ? v : 0.f;
                v += e1[(row/L)*D + col] + e2[col];
            }
            if (MODE == 5) {
                // row n of q -> (x,y,z); write x1[col][2x+p1][2y+p2][2z+p3]
                int x = row % VW, y = (row / VW) % VH, z = row / (VW*VH);
                size_t idx = (((size_t)col*SX + (2*x+p1))*SY + (2*y+p2))*SZ + (2*z+p3);
                C[idx] = v;
            } else {
                C[(size_t)row*N + col] = v;
            }
        }
    }
}

// ---------------- softmax over 12 per (query, head) ----------------
__global__ void k_softmax12(float* __restrict__ att)
{
    int i = blockIdx.x * blockDim.x + threadIdx.x;
    if (i >= NQ*HEADS) return;
    float* p = att + (size_t)(i/HEADS)*(HEADS*12) + (i%HEADS)*12;
    float mx = -1e30f;
    #pragma unroll
    for (int k = 0; k < 12; k++) mx = fmaxf(mx, p[k]);
    float s = 0.f;
    float e[12];
    #pragma unroll
    for (int k = 0; k < 12; k++) { e[k] = __expf(p[k]-mx); s += e[k]; }
    float inv = 1.f/s;
    #pragma unroll
    for (int k = 0; k < 12; k++) p[k] = e[k]*inv;
}

// ---------------- bilinear sampling + aggregation ----------------
__global__ void k_sample(const float* __restrict__ off, const float* __restrict__ att,
                         const float* __restrict__ val, float* __restrict__ agg)
{
    int n = blockIdx.x;
    int t = threadIdx.x;
    __shared__ float off_s[HEADS*CAMS*PTS*2];
    __shared__ float att_s[HEADS*CAMS*PTS];
    if (t < 192) off_s[t] = off[(size_t)n*192 + t];
    if (t < 96)  att_s[t] = att[(size_t)n*96 + t];
    __syncthreads();
    int h = t >> 5, dh = t & 31;
    int qx = n % VW, qy = (n / VW) % VH;
    float refx = (qx + 0.5f) * ((float)FW / VW) - 0.5f;
    float refy = (qy + 0.5f) * ((float)FH / VH) - 0.5f;
    float acc = 0.f;
    #pragma unroll
    for (int c = 0; c < CAMS; c++) {
        #pragma unroll
        for (int p = 0; p < PTS; p++) {
            int base = ((h*CAMS + c)*PTS + p)*2;
            float x = refx + off_s[base];
            float y = refy + off_s[base+1];
            float x0f = floorf(x), y0f = floorf(y);
            float wx = x - x0f, wy = y - y0f;
            int x0 = (int)x0f, y0 = (int)y0f;
            int xc0 = min(max(x0, 0), FW-1),   xc1 = min(max(x0+1, 0), FW-1);
            int yc0 = min(max(y0, 0), FH-1),   yc1 = min(max(y0+1, 0), FH-1);
            const float* vb = val + ((size_t)c*L*HEADS + h)*DH + dh;
            float v00 = vb[(size_t)(yc0*FW + xc0)*HEADS*DH];
            float v01 = vb[(size_t)(yc0*FW + xc1)*HEADS*DH];
            float v10 = vb[(size_t)(yc1*FW + xc0)*HEADS*DH];
            float v11 = vb[(size_t)(yc1*FW + xc1)*HEADS*DH];
            float bil = (1.f-wx)*(1.f-wy)*v00 + wx*(1.f-wy)*v01
                      + (1.f-wx)*wy*v10 + wx*wy*v11;
            acc += att_s[h*12 + c*2 + p] * bil;
        }
    }
    agg[(size_t)n*D + h*DH + dh] = acc;
}

// ---------------- layernorm (row of 256) ----------------
__global__ void k_ln(const float* __restrict__ in, float* __restrict__ out,
                     const float* __restrict__ g, const float* __restrict__ b)
{
    int n = blockIdx.x, t = threadIdx.x;
    float x = in[(size_t)n*D + t];
    float s = x, s2 = x*x;
    #pragma unroll
    for (int o = 16; o; o >>= 1) {
        s  += __shfl_xor_sync(0xffffffffu, s,  o);
        s2 += __shfl_xor_sync(0xffffffffu, s2, o);
    }
    __shared__ float ws[8], ws2[8], mv[2];
    if ((t & 31) == 0) { ws[t>>5] = s; ws2[t>>5] = s2; }
    __syncthreads();
    if (t < 32) {
        float a = (t < 8) ? ws[t] : 0.f, a2 = (t < 8) ? ws2[t] : 0.f;
        #pragma unroll
        for (int o = 4; o; o >>= 1) {
            a  += __shfl_xor_sync(0xffffffffu, a,  o);
            a2 += __shfl_xor_sync(0xffffffffu, a2, o);
        }
        if (t == 0) {
            float m = a / D;
            float v = a2 / D - m*m;
            mv[0] = m; mv[1] = rsqrtf(v + 1e-5f);
        }
    }
    __syncthreads();
    out[(size_t)n*D + t] = (x - mv[0]) * mv[1] * g[t] + b[t];
}

// ---------------- transpose deconv weights per parity ----------------
__global__ void k_wdt(const float* __restrict__ w, float* __restrict__ wdt)
{
    int i = blockIdx.x * blockDim.x + threadIdx.x;
    if (i >= 8*D*D) return;
    int o = i & 255, ic = (i >> 8) & 255, r = i >> 16;
    int r1 = (r >> 2) & 1, r2 = (r >> 1) & 1, r3 = r & 1;
    wdt[i] = w[((size_t)o*D + ic)*8 + ((1-r1)*4 + (1-r2)*2 + (1-r3))];
}

// ---------------- group norm ----------------
__global__ void k_gn_zero(double* sums) { if (threadIdx.x < 32) sums[threadIdx.x] = 0.0; }

__global__ void k_gn_stats(const float* __restrict__ x, double* __restrict__ sums, long glen)
{
    int g = blockIdx.x;
    const float* p = x + (size_t)g * glen;
    double s = 0.0, s2 = 0.0;
    for (long i = (long)blockIdx.y*blockDim.x + threadIdx.x; i < glen;
         i += (long)gridDim.y*blockDim.x) {
        float v = p[i];
        s += v; s2 += (double)v*v;
    }
    __shared__ double sh[256], sh2[256];
    sh[threadIdx.x] = s; sh2[threadIdx.x] = s2;
    __syncthreads();
    for (int o = 128; o; o >>= 1) {
        if (threadIdx.x < o) { sh[threadIdx.x] += sh[threadIdx.x+o]; sh2[threadIdx.x] += sh2[threadIdx.x+o]; }
        __syncthreads();
    }
    if (threadIdx.x == 0) {
        atomicAdd(&sums[g*2],   sh[0]);
        atomicAdd(&sums[g*2+1], sh2[0]);
    }
}

__global__ void k_gn_fin(const double* __restrict__ sums, float* __restrict__ mi, long glen)
{
    int g = threadIdx.x;
    if (g < 16) {
        double m = sums[g*2] / (double)glen;
        double v = sums[g*2+1] / (double)glen - m*m;
        mi[g*2]   = (float)m;
        mi[g*2+1] = (float)(1.0 / sqrt(v + 1e-5));
    }
}

__global__ void k_gn_apply(float* __restrict__ x, const float* __restrict__ mi,
                           const float* __restrict__ gg, const float* __restrict__ gb,
                           int cpg, long S, long total)
{
    for (long i = (long)blockIdx.x*blockDim.x + threadIdx.x; i < total;
         i += (long)gridDim.x*blockDim.x) {
        int c = (int)(i / S);
        int grp = c / cpg;
        float v = (x[i] - mi[grp*2]) * mi[grp*2+1] * gg[c] + gb[c];
        x[i] = v > 0.f ? v : 0.f;
    }
}

// ---------------- direct 3x3x3 conv, 256 -> 192 channels ----------------
#define COT 32      // output channels per block
#define CIB 8       // input channel chunk
#define CAT 2       // X tile
#define CBT 6       // Y tile
__global__ void k_conv3(const float* __restrict__ in, const float* __restrict__ w,
                        float* __restrict__ out)
{
    __shared__ float in_s[CIB][CAT+2][CBT+2][18];   // 4608 f
    __shared__ float w_s[COT][CIB][27];             // 6912 f
    int X0 = blockIdx.x * CAT;
    int Y0 = blockIdx.y * CBT;
    int oc0 = blockIdx.z * COT;
    int t = threadIdx.x;
    int ocp = t >> 4;       // 0..15
    int zz  = t & 15;       // 0..15
    float acc0[CAT][CBT] = {};
    float acc1[CAT][CBT] = {};
    for (int ic0 = 0; ic0 < X1_C; ic0 += CIB) {
        for (int i = t; i < CIB*(CAT+2)*(CBT+2)*18; i += 256) {
            int cc = i % 18;
            int r = i / 18;
            int bb = r % (CBT+2); r /= (CBT+2);
            int aa = r % (CAT+2);
            int ii = r / (CAT+2);
            int gx = X0 + aa - 1, gy = Y0 + bb - 1, gz = cc - 1;
            float v = 0.f;
            if (gx >= 0 && gx < SX && gy >= 0 && gy < SY && gz >= 0 && gz < SZ)
                v = in[(((size_t)(ic0+ii)*SX + gx)*SY + gy)*SZ + gz];
            in_s[ii][aa][bb][cc] = v;
        }
        for (int i = t; i < COT*CIB*27; i += 256) {
            int kk = i % 27; int r = i / 27;
            int ii = r % CIB; int oo = r / CIB;
            w_s[oo][ii][kk] = w[((size_t)(oc0+oo)*X1_C + (ic0+ii))*27 + kk];
        }
        __syncthreads();
        for (int ii = 0; ii < CIB; ii++) {
            #pragma unroll
            for (int kd = 0; kd < 3; kd++) {
                #pragma unroll
                for (int kh = 0; kh < 3; kh++) {
                    #pragma unroll
                    for (int kw = 0; kw < 3; kw++) {
                        float w0 = w_s[ocp][ii][(kd*3+kh)*3+kw];
                        float w1 = w_s[ocp+16][ii][(kd*3+kh)*3+kw];
                        #pragma unroll
                        for (int a = 0; a < CAT; a++) {
                            #pragma unroll
                            for (int b = 0; b < CBT; b++) {
                                float v = in_s[ii][a+kd][b+kh][zz+kw];
                                acc0[a][b] += w0*v;
                                acc1[a][b] += w1*v;
                            }
                        }
                    }
                }
            }
        }
        __syncthreads();
    }
    #pragma unroll
    for (int a = 0; a < CAT; a++) {
        int gx = X0 + a;
        #pragma unroll
        for (int b = 0; b < CBT; b++) {
            int gy = Y0 + b;
            if (gy < SY) {
                out[(((size_t)(oc0+ocp)*SX + gx)*SY + gy)*SZ + zz]    = acc0[a][b];
                out[(((size_t)(oc0+ocp+16)*SX + gx)*SY + gy)*SZ + zz] = acc1[a][b];
            }
        }
    }
}

// ---------------- host orchestration ----------------
extern "C" void kernel_launch(void* const* d_in, const int* in_sizes, int n_in,
                              void* d_out, int out_size)
{
    // Robust input indexing: img_h / img_w are python scalars. If the harness
    // materializes them as 1-element buffers they sit at indices 2,3; if it
    // drops scalars, everything after index 1 shifts down by 2.
    int shift = 0;
    if (n_in >= 4 && in_sizes[2] == 1 && in_sizes[3] == 1) shift = 0;
    else shift = 2;
    #define IN(i) ((i) >= 2 ? d_in[(i) - shift] : d_in[(i)])

    const float* camera_x  = (const float*)IN(0);
    const int*   ids       = (const int*)  IN(1);
    const float* mask_tok  = (const float*)IN(4);
    const float* vol_emb   = (const float*)IN(5);
    const float* W_tc      = (const float*)IN(6);
    const float* b_tc      = (const float*)IN(7);
    const float* cams_emb  = (const float*)IN(8);
    const float* lvl_emb   = (const float*)IN(9);
    const float* W_off     = (const float*)IN(10);
    const float* b_off     = (const float*)IN(11);
    const float* W_att     = (const float*)IN(12);
    const float* b_att     = (const float*)IN(13);
    const float* W_val     = (const float*)IN(14);
    const float* b_val     = (const float*)IN(15);
    const float* W_out     = (const float*)IN(16);
    const float* b_out     = (const float*)IN(17);
    const float* ln1_g     = (const float*)IN(18);
    const float* ln1_b     = (const float*)IN(19);
    const float* W_ff1     = (const float*)IN(20);
    const float* b_ff1     = (const float*)IN(21);
    const float* W_ff2     = (const float*)IN(22);
    const float* b_ff2     = (const float*)IN(23);
    const float* ln2_g     = (const float*)IN(24);
    const float* ln2_b     = (const float*)IN(25);
    const float* deconv_w  = (const float*)IN(26);
    const float* gn1_g     = (const float*)IN(27);
    const float* gn1_b     = (const float*)IN(28);
    const float* conv3_w   = (const float*)IN(29);
    const float* gn2_g     = (const float*)IN(30);
    const float* gn2_b     = (const float*)IN(31);
    #undef IN

    float* out = (float*)d_out;

    float *p_full, *p_feat, *p_val, *p_off, *p_att, *p_agg, *p_q, *p_qt, *p_h1, *p_wdt, *p_x1, *p_mi;
    double* p_sum;
    cudaGetSymbolAddress((void**)&p_full, g_full);
    cudaGetSymbolAddress((void**)&p_feat, g_feat);
    cudaGetSymbolAddress((void**)&p_val,  g_val);
    cudaGetSymbolAddress((void**)&p_off,  g_off);
    cudaGetSymbolAddress((void**)&p_att,  g_att);
    cudaGetSymbolAddress((void**)&p_agg,  g_agg);
    cudaGetSymbolAddress((void**)&p_q,    g_q);
    cudaGetSymbolAddress((void**)&p_qt,   g_qt);
    cudaGetSymbolAddress((void**)&p_h1,   g_h1);
    cudaGetSymbolAddress((void**)&p_wdt,  g_wdt);
    cudaGetSymbolAddress((void**)&p_x1,   g_x1);
    cudaGetSymbolAddress((void**)&p_sum,  g_gnsum);
    cudaGetSymbolAddress((void**)&p_mi,   g_gnmi);

    // stage A: restore + cam_x output
    k_restore<<<CAMS*L, 256>>>(camera_x, ids, mask_tok, p_full, out + XOUT_SZ);

    // stage B: feature projection (W_tc is (N,K) -> TB)
    gemm_k<4, true><<<dim3(4, 17), 256>>>(p_full, W_tc, p_feat, CAMS*L, D, IN_C,
                                          b_tc, nullptr, cams_emb, lvl_emb, 0, 0, 0);

    // q init
    cudaMemcpyAsync(p_q, vol_emb, (size_t)NQ*D*sizeof(float), cudaMemcpyDeviceToDevice);

    const int MB = (NQ + TM - 1) / TM;   // 313
    for (int l = 0; l < LAYERS; l++) {
        gemm_k<1, false><<<dim3(4, 17), 256>>>(p_feat, W_val + (size_t)l*D*D, p_val,
                                               CAMS*L, D, D, b_val + l*D, nullptr, nullptr, nullptr, 0,0,0);
        gemm_k<1, false><<<dim3(3, MB), 256>>>(p_q, W_off + (size_t)l*D*192, p_off,
                                               NQ, 192, D, b_off + l*192, nullptr, nullptr, nullptr, 0,0,0);
        gemm_k<1, false><<<dim3(2, MB), 256>>>(p_q, W_att + (size_t)l*D*96, p_att,
                                               NQ, 96, D, b_att + l*96, nullptr, nullptr, nullptr, 0,0,0);
        k_softmax12<<<(NQ*HEADS + 255)/256, 256>>>(p_att);
        k_sample<<<NQ, 256>>>(p_off, p_att, p_val, p_agg);
        gemm_k<3, false><<<dim3(4, MB), 256>>>(p_agg, W_out + (size_t)l*D*D, p_qt,
                                               NQ, D, D, b_out + l*D, p_q, nullptr, nullptr, 0,0,0);
        k_ln<<<NQ, 256>>>(p_qt, p_q, ln1_g + l*D, ln1_b + l*D);
        gemm_k<2, false><<<dim3(8, MB), 256>>>(p_q, W_ff1 + (size_t)l*D*FFN, p_h1,
                                               NQ, FFN, D, b_ff1 + l*FFN, nullptr, nullptr, nullptr, 0,0,0);
        gemm_k<3, false><<<dim3(4, MB), 256>>>(p_h1, W_ff2 + (size_t)l*FFN*D, p_qt,
                                               NQ, D, FFN, b_ff2 + l*D, p_q, nullptr, nullptr, 0,0,0);
        k_ln<<<NQ, 256>>>(p_qt, p_q, ln2_g + l*D, ln2_b + l*D);
    }

    // deconv (transposed conv) as 8 parity GEMMs
    k_wdt<<<(8*D*D + 255)/256, 256>>>(deconv_w, p_wdt);
    for (int r = 0; r < 8; r++) {
        gemm_k<5, false><<<dim3(4, MB), 256>>>(p_q, p_wdt + (size_t)r*D*D, p_x1,
                                               NQ, D, D, nullptr, nullptr, nullptr, nullptr,
                                               (r >> 2) & 1, (r >> 1) & 1, r & 1);
    }

    // group norm 1 + relu (in place on x1), 16 groups x 16 ch
    {
        long glen = 16L * (long)SPAT;   // 2.56M per group
        k_gn_zero<<<1, 32>>>(p_sum);
        k_gn_stats<<<dim3(16, 64), 256>>>(p_x1, p_sum, glen);
        k_gn_fin<<<1, 32>>>(p_sum, p_mi, glen);
        k_gn_apply<<<4096, 256>>>(p_x1, p_mi, gn1_g, gn1_b, 16, (long)SPAT, (long)X1_C*SPAT);
    }

    // conv3 -> d_out (first region)
    k_conv3<<<dim3(SX/CAT, (SY + CBT - 1)/CBT, OC3/COT), 256>>>(p_x1, conv3_w, out);

    // group norm 2 + relu (in place on d_out), 16 groups x 12 ch
    {
        long glen = 12L * (long)SPAT;
        k_gn_zero<<<1, 32>>>(p_sum);
        k_gn_stats<<<dim3(16, 64), 256>>>(out, p_sum, glen);
        k_gn_fin<<<1, 32>>>(p_sum, p_mi, glen);
        k_gn_apply<<<4096, 256>>>(out, p_mi, gn2_g, gn2_b, 12, (long)SPAT, (long)OC3*SPAT);
    }
}

// round 3
// speedup vs baseline: 1.1939x; 1.1939x over previous
#include <cuda_runtime.h>
#include <cuda_bf16.h>
#include <cstddef>

// ---------------- problem constants ----------------
#define CAMS 6
#define HEADS 8
#define PTS 2
#define LAYERS 3
#define D 256
#define DH 32
#define FFN 512
#define VZ 8
#define VH 50
#define VW 50
#define NQ (VZ*VH*VW)          // 20000
#define IN_C 768
#define FH 8
#define FW 22
#define L 176                   // FH*FW
#define LVIS 44

#define X1_C 256
#define SX 100
#define SY 100
#define SZ 16
#define SPAT ((size_t)SX*SY*SZ)   // 160000
#define OC3 192

#define XOUT_SZ ((size_t)OC3*SPAT)          // 30,720,000
#define CAMX_SZ ((size_t)CAMS*IN_C*L)       // 811,008

// padded split-input for conv3 implicit GEMM
#define XP 102
#define YP 102
#define ZP 18
#define PSPAT ((size_t)XP*YP*ZP)            // 187,272

// ---------------- scratch (static device globals; no allocation) ----------------
__device__ float g_full[CAMS*L*IN_C];
__device__ float g_feat[CAMS*L*D];
__device__ float g_val [CAMS*L*D];
__device__ float g_off [NQ*HEADS*CAMS*PTS*2];
__device__ float g_att [NQ*HEADS*CAMS*PTS];
__device__ float g_agg [NQ*D];
__device__ float g_q   [NQ*D];
__device__ float g_qt  [NQ*D];
__device__ float g_h1  [NQ*FFN];
__device__ float g_wdt [8*D*D];
__device__ float g_x1  [(size_t)X1_C*SX*SY*SZ];   // 40.96M floats
__device__ unsigned g_xpad[(size_t)X1_C*PSPAT];   // packed bf16 (hi|lo<<16), padded
__device__ unsigned g_wsp [27*OC3*X1_C];          // packed bf16 weights per tap
__device__ double g_gnsum[32];
__device__ float  g_gnmi[32];

// ---------------- restore tokens + write cam_x output ----------------
__global__ void k_restore(const float* __restrict__ camx,
                          const int* __restrict__ ids,
                          const float* __restrict__ mask_tok,
                          float* __restrict__ full,
                          float* __restrict__ camx_out)
{
    int tok = blockIdx.x;            // 0..1055
    int n = tok / L, p = tok % L;
    int t = ids[n*L + p];
    for (int c = threadIdx.x; c < IN_C; c += blockDim.x) {
        float v = (t < LVIS) ? camx[((size_t)n*LVIS + t)*IN_C + c] : mask_tok[c];
        full[(size_t)tok*IN_C + c] = v;
        camx_out[((size_t)n*IN_C + c)*L + p] = v;
    }
}

// ---------------- generic tiled SGEMM  C = A(MxK) @ B(KxN), epilogues ----------------
// MODE: 0 none, 1 +bias, 2 relu(+bias), 3 +bias+res, 4 feat, 5 deconv scatter
#define TM 64
#define TN 64
#define TKK 16
template<int MODE, bool TB>
__global__ void gemm_k(const float* __restrict__ A, const float* __restrict__ B,
                       float* __restrict__ C, int M, int N, int K,
                       const float* __restrict__ bias, const float* __restrict__ res,
                       const float* __restrict__ e1, const float* __restrict__ e2,
                       int p1, int p2, int p3)
{
    __shared__ float As[TKK][TM+4];
    __shared__ float Bs[TKK][TN+4];
    int m0 = blockIdx.y * TM, n0 = blockIdx.x * TN;
    int t = threadIdx.x;
    int tx = t & 15, ty = t >> 4;
    float acc[4][4] = {};
    for (int k0 = 0; k0 < K; k0 += TKK) {
        for (int i = t; i < TM*TKK; i += 256) {
            int mm = i >> 4, kk = i & 15;
            int m = m0 + mm, k = k0 + kk;
            As[kk][mm] = (m < M && k < K) ? A[(size_t)m*K + k] : 0.f;
        }
        if (!TB) {
            for (int i = t; i < TKK*TN; i += 256) {
                int kk = i >> 6, nn = i & 63;
                int k = k0 + kk, n = n0 + nn;
                Bs[kk][nn] = (k < K && n < N) ? B[(size_t)k*N + n] : 0.f;
            }
        } else {
            for (int i = t; i < TKK*TN; i += 256) {
                int nn = i >> 4, kk = i & 15;
                int k = k0 + kk, n = n0 + nn;
                Bs[kk][nn] = (k < K && n < N) ? B[(size_t)n*K + k] : 0.f;
            }
        }
        __syncthreads();
        #pragma unroll
        for (int kk = 0; kk < TKK; kk++) {
            float a[4], b[4];
            #pragma unroll
            for (int i = 0; i < 4; i++) a[i] = As[kk][ty*4 + i];
            #pragma unroll
            for (int j = 0; j < 4; j++) b[j] = Bs[kk][tx*4 + j];
            #pragma unroll
            for (int i = 0; i < 4; i++)
                #pragma unroll
                for (int j = 0; j < 4; j++) acc[i][j] += a[i]*b[j];
        }
        __syncthreads();
    }
    #pragma unroll
    for (int i = 0; i < 4; i++) {
        int row = m0 + ty*4 + i;
        if (row >= M) continue;
        #pragma unroll
        for (int j = 0; j < 4; j++) {
            int col = n0 + tx*4 + j;
            if (col >= N) continue;
            float v = acc[i][j];
            if (MODE == 1) v += bias[col];
            else if (MODE == 2) { v += bias[col]; v = v > 0.f ? v : 0.f; }
            else if (MODE == 3) v += bias[col] + res[(size_t)row*N + col];
            else if (MODE == 4) {
                v += bias[col]; v = v > 0.f ? v : 0.f;
                v += e1[(row/L)*D + col] + e2[col];
            }
            if (MODE == 5) {
                int x = row % VW, y = (row / VW) % VH, z = row / (VW*VH);
                size_t idx = (((size_t)col*SX + (2*x+p1))*SY + (2*y+p2))*SZ + (2*z+p3);
                C[idx] = v;
            } else {
                C[(size_t)row*N + col] = v;
            }
        }
    }
}

// ---------------- softmax over 12 per (query, head) ----------------
__global__ void k_softmax12(float* __restrict__ att)
{
    int i = blockIdx.x * blockDim.x + threadIdx.x;
    if (i >= NQ*HEADS) return;
    float* p = att + (size_t)(i/HEADS)*(HEADS*12) + (i%HEADS)*12;
    float mx = -1e30f;
    #pragma unroll
    for (int k = 0; k < 12; k++) mx = fmaxf(mx, p[k]);
    float s = 0.f;
    float e[12];
    #pragma unroll
    for (int k = 0; k < 12; k++) { e[k] = __expf(p[k]-mx); s += e[k]; }
    float inv = 1.f/s;
    #pragma unroll
    for (int k = 0; k < 12; k++) p[k] = e[k]*inv;
}

// ---------------- bilinear sampling + aggregation ----------------
__global__ void k_sample(const float* __restrict__ off, const float* __restrict__ att,
                         const float* __restrict__ val, float* __restrict__ agg)
{
    int n = blockIdx.x;
    int t = threadIdx.x;
    __shared__ float off_s[HEADS*CAMS*PTS*2];
    __shared__ float att_s[HEADS*CAMS*PTS];
    if (t < 192) off_s[t] = off[(size_t)n*192 + t];
    if (t < 96)  att_s[t] = att[(size_t)n*96 + t];
    __syncthreads();
    int h = t >> 5, dh = t & 31;
    int qx = n % VW, qy = (n / VW) % VH;
    float refx = (qx + 0.5f) * ((float)FW / VW) - 0.5f;
    float refy = (qy + 0.5f) * ((float)FH / VH) - 0.5f;
    float acc = 0.f;
    #pragma unroll
    for (int c = 0; c < CAMS; c++) {
        #pragma unroll
        for (int p = 0; p < PTS; p++) {
            int base = ((h*CAMS + c)*PTS + p)*2;
            float x = refx + off_s[base];
            float y = refy + off_s[base+1];
            float x0f = floorf(x), y0f = floorf(y);
            float wx = x - x0f, wy = y - y0f;
            int x0 = (int)x0f, y0 = (int)y0f;
            int xc0 = min(max(x0, 0), FW-1),   xc1 = min(max(x0+1, 0), FW-1);
            int yc0 = min(max(y0, 0), FH-1),   yc1 = min(max(y0+1, 0), FH-1);
            const float* vb = val + ((size_t)c*L*HEADS + h)*DH + dh;
            float v00 = vb[(size_t)(yc0*FW + xc0)*HEADS*DH];
            float v01 = vb[(size_t)(yc0*FW + xc1)*HEADS*DH];
            float v10 = vb[(size_t)(yc1*FW + xc0)*HEADS*DH];
            float v11 = vb[(size_t)(yc1*FW + xc1)*HEADS*DH];
            float bil = (1.f-wx)*(1.f-wy)*v00 + wx*(1.f-wy)*v01
                      + (1.f-wx)*wy*v10 + wx*wy*v11;
            acc += att_s[h*12 + c*2 + p] * bil;
        }
    }
    agg[(size_t)n*D + h*DH + dh] = acc;
}

// ---------------- layernorm (row of 256) ----------------
__global__ void k_ln(const float* __restrict__ in, float* __restrict__ out,
                     const float* __restrict__ g, const float* __restrict__ b)
{
    int n = blockIdx.x, t = threadIdx.x;
    float x = in[(size_t)n*D + t];
    float s = x, s2 = x*x;
    #pragma unroll
    for (int o = 16; o; o >>= 1) {
        s  += __shfl_xor_sync(0xffffffffu, s,  o);
        s2 += __shfl_xor_sync(0xffffffffu, s2, o);
    }
    __shared__ float ws[8], ws2[8], mv[2];
    if ((t & 31) == 0) { ws[t>>5] = s; ws2[t>>5] = s2; }
    __syncthreads();
    if (t < 32) {
        float a = (t < 8) ? ws[t] : 0.f, a2 = (t < 8) ? ws2[t] : 0.f;
        #pragma unroll
        for (int o = 4; o; o >>= 1) {
            a  += __shfl_xor_sync(0xffffffffu, a,  o);
            a2 += __shfl_xor_sync(0xffffffffu, a2, o);
        }
        if (t == 0) {
            float m = a / D;
            float v = a2 / D - m*m;
            mv[0] = m; mv[1] = rsqrtf(v + 1e-5f);
        }
    }
    __syncthreads();
    out[(size_t)n*D + t] = (x - mv[0]) * mv[1] * g[t] + b[t];
}

// ---------------- transpose deconv weights per parity ----------------
__global__ void k_wdt(const float* __restrict__ w, float* __restrict__ wdt)
{
    int i = blockIdx.x * blockDim.x + threadIdx.x;
    if (i >= 8*D*D) return;
    int o = i & 255, ic = (i >> 8) & 255, r = i >> 16;
    int r1 = (r >> 2) & 1, r2 = (r >> 1) & 1, r3 = r & 1;
    wdt[i] = w[((size_t)o*D + ic)*8 + ((1-r1)*4 + (1-r2)*2 + (1-r3))];
}

// ---------------- group norm ----------------
__global__ void k_gn_zero(double* sums) { if (threadIdx.x < 32) sums[threadIdx.x] = 0.0; }

__global__ void k_gn_stats(const float* __restrict__ x, double* __restrict__ sums, long glen)
{
    int g = blockIdx.x;
    const float* p = x + (size_t)g * glen;
    double s = 0.0, s2 = 0.0;
    for (long i = (long)blockIdx.y*blockDim.x + threadIdx.x; i < glen;
         i += (long)gridDim.y*blockDim.x) {
        float v = p[i];
        s += v; s2 += (double)v*v;
    }
    __shared__ double sh[256], sh2[256];
    sh[threadIdx.x] = s; sh2[threadIdx.x] = s2;
    __syncthreads();
    for (int o = 128; o; o >>= 1) {
        if (threadIdx.x < o) { sh[threadIdx.x] += sh[threadIdx.x+o]; sh2[threadIdx.x] += sh2[threadIdx.x+o]; }
        __syncthreads();
    }
    if (threadIdx.x == 0) {
        atomicAdd(&sums[g*2],   sh[0]);
        atomicAdd(&sums[g*2+1], sh2[0]);
    }
}

__global__ void k_gn_fin(const double* __restrict__ sums, float* __restrict__ mi, long glen)
{
    int g = threadIdx.x;
    if (g < 16) {
        double m = sums[g*2] / (double)glen;
        double v = sums[g*2+1] / (double)glen - m*m;
        mi[g*2]   = (float)m;
        mi[g*2+1] = (float)(1.0 / sqrt(v + 1e-5));
    }
}

__global__ void k_gn_apply(float* __restrict__ x, const float* __restrict__ mi,
                           const float* __restrict__ gg, const float* __restrict__ gb,
                           int cpg, long S, long total)
{
    for (long i = (long)blockIdx.x*blockDim.x + threadIdx.x; i < total;
         i += (long)gridDim.x*blockDim.x) {
        int c = (int)(i / S);
        int grp = c / cpg;
        float v = (x[i] - mi[grp*2]) * mi[grp*2+1] * gg[c] + gb[c];
        x[i] = v > 0.f ? v : 0.f;
    }
}

// ---------------- conv3 prep: pad + bf16 hi/lo split ----------------
__device__ __forceinline__ unsigned pack_split(float v)
{
    __nv_bfloat16 h = __float2bfloat16(v);
    float fh = __bfloat162float(h);
    __nv_bfloat16 l = __float2bfloat16(v - fh);
    return (unsigned)__bfloat16_as_ushort(h) | ((unsigned)__bfloat16_as_ushort(l) << 16);
}

__global__ void k_prep(const float* __restrict__ x1, unsigned* __restrict__ xp)
{
    long i = (long)blockIdx.x * blockDim.x + threadIdx.x;
    if (i >= (long)X1_C*SPAT) return;
    int z = (int)(i & 15); long t = i >> 4;
    int y = (int)(t % SY); t /= SY;
    int x = (int)(t % SX); int ic = (int)(t / SX);
    xp[(size_t)ic*PSPAT + ((size_t)(x+1)*YP + (y+1))*ZP + (z+1)] = pack_split(x1[i]);
}

__global__ void k_wprep(const float* __restrict__ w, unsigned* __restrict__ wsp)
{
    int i = blockIdx.x * blockDim.x + threadIdx.x;
    if (i >= 27*OC3*X1_C) return;
    int ic = i & 255; int t = i >> 8;
    int oc = t % OC3; int tap = t / OC3;
    wsp[(size_t)tap*OC3*X1_C + oc*X1_C + ic] = pack_split(w[((size_t)oc*X1_C + ic)*27 + tap]);
}

// ---------------- conv3 via mma.sync bf16 (3-term hi/lo split) ----------------
// Output tile: 2x x 4y x 16z (M=128) x all 192 oc (N). K = 27 taps x 256 ic.
#define ICP 18          // padded ic stride (ushorts) per smem row
#define AROWS 432       // 4x * 6y * 18z

__device__ __forceinline__ void mma_bf16(float* c, const unsigned* a, const unsigned* b)
{
    asm volatile(
        "mma.sync.aligned.m16n8k16.row.col.f32.bf16.bf16.f32 "
        "{%0,%1,%2,%3}, {%4,%5,%6,%7}, {%8,%9}, {%0,%1,%2,%3};\n"
        : "+f"(c[0]), "+f"(c[1]), "+f"(c[2]), "+f"(c[3])
        : "r"(a[0]), "r"(a[1]), "r"(a[2]), "r"(a[3]), "r"(b[0]), "r"(b[1]));
}

__global__ __launch_bounds__(512) void k_conv3_mma(const unsigned* __restrict__ xp,
                                                   const unsigned* __restrict__ wsp,
                                                   float* __restrict__ out)
{
    __shared__ unsigned short As_hi[AROWS*ICP];
    __shared__ unsigned short As_lo[AROWS*ICP];
    __shared__ unsigned short Ws_hi[OC3*ICP];
    __shared__ unsigned short Ws_lo[OC3*ICP];

    int x0 = blockIdx.x * 2, y0 = blockIdx.y * 4;
    int tid = threadIdx.x, lane = tid & 31, wrp = tid >> 5;
    int warp_m = wrp & 3, warp_n = wrp >> 2;       // 4 x 4 warp grid
    int q = lane & 3, rr = lane >> 2;
    int xo = warp_m >> 1;

    float acc[2][6][4];
    #pragma unroll
    for (int f = 0; f < 2; f++)
        #pragma unroll
        for (int j = 0; j < 6; j++)
            #pragma unroll
            for (int k = 0; k < 4; k++) acc[f][j][k] = 0.f;

    const unsigned* ph = (const unsigned*)As_hi;
    const unsigned* pl = (const unsigned*)As_lo;
    const unsigned* qh = (const unsigned*)Ws_hi;
    const unsigned* ql = (const unsigned*)Ws_lo;

    for (int ic0 = 0; ic0 < X1_C; ic0 += 16) {
        __syncthreads();
        // load A region: 4x * 6y * 18z * 16ic packed words; split into hi/lo smem
        for (int i = tid; i < 6912; i += 512) {
            int rz = i % 18; int t1 = i / 18;
            int ry = t1 % 6; int t2 = t1 / 6;
            int rx = t2 & 3; int ic = t2 >> 2;
            unsigned v = xp[(size_t)(ic0+ic)*PSPAT + ((size_t)(x0+rx)*YP + (y0+ry))*ZP + rz];
            int row = (rx*6 + ry)*18 + rz;
            As_hi[row*ICP + ic] = (unsigned short)(v & 0xffffu);
            As_lo[row*ICP + ic] = (unsigned short)(v >> 16);
        }
        for (int tap = 0; tap < 27; tap++) {
            __syncthreads();
            for (int i = tid; i < 3072; i += 512) {
                int ic = i & 15, oc = i >> 4;
                unsigned v = wsp[(size_t)tap*OC3*X1_C + oc*X1_C + ic0 + ic];
                Ws_hi[oc*ICP + ic] = (unsigned short)(v & 0xffffu);
                Ws_lo[oc*ICP + ic] = (unsigned short)(v >> 16);
            }
            __syncthreads();
            int k1 = tap / 9, k2 = (tap / 3) % 3, k3 = tap % 3;

            // A fragments (2 m-frags, hi+lo). rows: z = rr and rr+8.
            unsigned ah[2][4], al[2][4];
            #pragma unroll
            for (int f = 0; f < 2; f++) {
                int yo = (warp_m & 1)*2 + f;
                int rowa = ((xo + k1)*6 + (yo + k2))*18 + rr + k3;
                int rowb = rowa + 8;
                ah[f][0] = ph[rowa*9 + q];     ah[f][1] = ph[rowb*9 + q];
                ah[f][2] = ph[rowa*9 + q + 4]; ah[f][3] = ph[rowb*9 + q + 4];
                al[f][0] = pl[rowa*9 + q];     al[f][1] = pl[rowb*9 + q];
                al[f][2] = pl[rowa*9 + q + 4]; al[f][3] = pl[rowb*9 + q + 4];
            }
            // B fragments (6 n-frags, hi+lo)
            unsigned bh[6][2], bl[6][2];
            #pragma unroll
            for (int j = 0; j < 6; j++) {
                int n = warp_n*48 + j*8 + rr;
                bh[j][0] = qh[n*9 + q]; bh[j][1] = qh[n*9 + q + 4];
                bl[j][0] = ql[n*9 + q]; bl[j][1] = ql[n*9 + q + 4];
            }
            #pragma unroll
            for (int f = 0; f < 2; f++)
                #pragma unroll
                for (int j = 0; j < 6; j++) {
                    mma_bf16(acc[f][j], ah[f], bh[j]);   // hi * w_hi
                    mma_bf16(acc[f][j], ah[f], bl[j]);   // hi * w_lo
                    mma_bf16(acc[f][j], al[f], bh[j]);   // lo * w_hi
                }
        }
    }

    // epilogue: c0=(z=rr,oc) c1=(rr,oc+1) c2=(rr+8,oc) c3=(rr+8,oc+1)
    #pragma unroll
    for (int f = 0; f < 2; f++) {
        int yo = (warp_m & 1)*2 + f;
        int X = x0 + xo, Y = y0 + yo;
        #pragma unroll
        for (int j = 0; j < 6; j++) {
            int oc = warp_n*48 + j*8 + 2*q;
            size_t base = (((size_t)oc*SX + X)*SY + Y)*SZ;
            out[base + rr]            = acc[f][j][0];
            out[base + rr + 8]        = acc[f][j][2];
            out[base + SPAT + rr]     = acc[f][j][1];
            out[base + SPAT + rr + 8] = acc[f][j][3];
        }
    }
}

// ---------------- host orchestration ----------------
extern "C" void kernel_launch(void* const* d_in, const int* in_sizes, int n_in,
                              void* d_out, int out_size)
{
    int shift = 0;
    if (n_in >= 4 && in_sizes[2] == 1 && in_sizes[3] == 1) shift = 0;
    else shift = 2;
    #define IN(i) ((i) >= 2 ? d_in[(i) - shift] : d_in[(i)])

    const float* camera_x  = (const float*)IN(0);
    const int*   ids       = (const int*)  IN(1);
    const float* mask_tok  = (const float*)IN(4);
    const float* vol_emb   = (const float*)IN(5);
    const float* W_tc      = (const float*)IN(6);
    const float* b_tc      = (const float*)IN(7);
    const float* cams_emb  = (const float*)IN(8);
    const float* lvl_emb   = (const float*)IN(9);
    const float* W_off     = (const float*)IN(10);
    const float* b_off     = (const float*)IN(11);
    const float* W_att     = (const float*)IN(12);
    const float* b_att     = (const float*)IN(13);
    const float* W_val     = (const float*)IN(14);
    const float* b_val     = (const float*)IN(15);
    const float* W_out     = (const float*)IN(16);
    const float* b_out     = (const float*)IN(17);
    const float* ln1_g     = (const float*)IN(18);
    const float* ln1_b     = (const float*)IN(19);
    const float* W_ff1     = (const float*)IN(20);
    const float* b_ff1     = (const float*)IN(21);
    const float* W_ff2     = (const float*)IN(22);
    const float* b_ff2     = (const float*)IN(23);
    const float* ln2_g     = (const float*)IN(24);
    const float* ln2_b     = (const float*)IN(25);
    const float* deconv_w  = (const float*)IN(26);
    const float* gn1_g     = (const float*)IN(27);
    const float* gn1_b     = (const float*)IN(28);
    const float* conv3_w   = (const float*)IN(29);
    const float* gn2_g     = (const float*)IN(30);
    const float* gn2_b     = (const float*)IN(31);
    #undef IN

    float* out = (float*)d_out;

    float *p_full, *p_feat, *p_val, *p_off, *p_att, *p_agg, *p_q, *p_qt, *p_h1, *p_wdt, *p_x1, *p_mi;
    unsigned *p_xpad, *p_wsp;
    double* p_sum;
    cudaGetSymbolAddress((void**)&p_full, g_full);
    cudaGetSymbolAddress((void**)&p_feat, g_feat);
    cudaGetSymbolAddress((void**)&p_val,  g_val);
    cudaGetSymbolAddress((void**)&p_off,  g_off);
    cudaGetSymbolAddress((void**)&p_att,  g_att);
    cudaGetSymbolAddress((void**)&p_agg,  g_agg);
    cudaGetSymbolAddress((void**)&p_q,    g_q);
    cudaGetSymbolAddress((void**)&p_qt,   g_qt);
    cudaGetSymbolAddress((void**)&p_h1,   g_h1);
    cudaGetSymbolAddress((void**)&p_wdt,  g_wdt);
    cudaGetSymbolAddress((void**)&p_x1,   g_x1);
    cudaGetSymbolAddress((void**)&p_xpad, g_xpad);
    cudaGetSymbolAddress((void**)&p_wsp,  g_wsp);
    cudaGetSymbolAddress((void**)&p_sum,  g_gnsum);
    cudaGetSymbolAddress((void**)&p_mi,   g_gnmi);

    // zero padded buffer (halo must be 0; interior is overwritten by k_prep)
    cudaMemsetAsync(p_xpad, 0, (size_t)X1_C*PSPAT*sizeof(unsigned));

    // conv weight split (independent of everything else)
    k_wprep<<<(27*OC3*X1_C + 255)/256, 256>>>(conv3_w, p_wsp);

    // stage A: restore + cam_x output
    k_restore<<<CAMS*L, 256>>>(camera_x, ids, mask_tok, p_full, out + XOUT_SZ);

    // stage B: feature projection (W_tc is (N,K) -> TB)
    gemm_k<4, true><<<dim3(4, 17), 256>>>(p_full, W_tc, p_feat, CAMS*L, D, IN_C,
                                          b_tc, nullptr, cams_emb, lvl_emb, 0, 0, 0);

    // q init
    cudaMemcpyAsync(p_q, vol_emb, (size_t)NQ*D*sizeof(float), cudaMemcpyDeviceToDevice);

    const int MB = (NQ + TM - 1) / TM;   // 313
    for (int l = 0; l < LAYERS; l++) {
        gemm_k<1, false><<<dim3(4, 17), 256>>>(p_feat, W_val + (size_t)l*D*D, p_val,
                                               CAMS*L, D, D, b_val + l*D, nullptr, nullptr, nullptr, 0,0,0);
        gemm_k<1, false><<<dim3(3, MB), 256>>>(p_q, W_off + (size_t)l*D*192, p_off,
                                               NQ, 192, D, b_off + l*192, nullptr, nullptr, nullptr, 0,0,0);
        gemm_k<1, false><<<dim3(2, MB), 256>>>(p_q, W_att + (size_t)l*D*96, p_att,
                                               NQ, 96, D, b_att + l*96, nullptr, nullptr, nullptr, 0,0,0);
        k_softmax12<<<(NQ*HEADS + 255)/256, 256>>>(p_att);
        k_sample<<<NQ, 256>>>(p_off, p_att, p_val, p_agg);
        gemm_k<3, false><<<dim3(4, MB), 256>>>(p_agg, W_out + (size_t)l*D*D, p_qt,
                                               NQ, D, D, b_out + l*D, p_q, nullptr, nullptr, 0,0,0);
        k_ln<<<NQ, 256>>>(p_qt, p_q, ln1_g + l*D, ln1_b + l*D);
        gemm_k<2, false><<<dim3(8, MB), 256>>>(p_q, W_ff1 + (size_t)l*D*FFN, p_h1,
                                               NQ, FFN, D, b_ff1 + l*FFN, nullptr, nullptr, nullptr, 0,0,0);
        gemm_k<3, false><<<dim3(4, MB), 256>>>(p_h1, W_ff2 + (size_t)l*FFN*D, p_qt,
                                               NQ, D, FFN, b_ff2 + l*D, p_q, nullptr, nullptr, 0,0,0);
        k_ln<<<NQ, 256>>>(p_qt, p_q, ln2_g + l*D, ln2_b + l*D);
    }

    // deconv (transposed conv) as 8 parity GEMMs
    k_wdt<<<(8*D*D + 255)/256, 256>>>(deconv_w, p_wdt);
    for (int r = 0; r < 8; r++) {
        gemm_k<5, false><<<dim3(4, MB), 256>>>(p_q, p_wdt + (size_t)r*D*D, p_x1,
                                               NQ, D, D, nullptr, nullptr, nullptr, nullptr,
                                               (r >> 2) & 1, (r >> 1) & 1, r & 1);
    }

    // group norm 1 + relu (in place on x1), 16 groups x 16 ch
    {
        long glen = 16L * (long)SPAT;   // 2.56M per group
        k_gn_zero<<<1, 32>>>(p_sum);
        k_gn_stats<<<dim3(16, 64), 256>>>(p_x1, p_sum, glen);
        k_gn_fin<<<1, 32>>>(p_sum, p_mi, glen);
        k_gn_apply<<<4096, 256>>>(p_x1, p_mi, gn1_g, gn1_b, 16, (long)SPAT, (long)X1_C*SPAT);
    }

    // conv3 input prep: pad + bf16 split
    k_prep<<<(int)(((long)X1_C*SPAT + 255)/256), 256>>>(p_x1, p_xpad);

    // conv3 -> d_out via tensor cores
    k_conv3_mma<<<dim3(SX/2, SY/4), 512>>>(p_xpad, p_wsp, out);

    // group norm 2 + relu (in place on d_out), 16 groups x 12 ch
    {
        long glen = 12L * (long)SPAT;
        k_gn_zero<<<1, 32>>>(p_sum);
        k_gn_stats<<<dim3(16, 64), 256>>>(out, p_sum, glen);
        k_gn_fin<<<1, 32>>>(p_sum, p_mi, glen);
        k_gn_apply<<<4096, 256>>>(out, p_mi, gn2_g, gn2_b, 12, (long)SPAT, (long)OC3*SPAT);
    }
}

// round 6
// speedup vs baseline: 2.6159x; 2.1911x over previous
#include <cuda_runtime.h>
#include <cuda_bf16.h>
#include <cstddef>
#include <cstdint>

typedef unsigned short u16;

// ---------------- problem constants ----------------
#define CAMS 6
#define HEADS 8
#define PTS 2
#define LAYERS 3
#define D 256
#define DH 32
#define FFN 512
#define VZ 8
#define VH 50
#define VW 50
#define NQ (VZ*VH*VW)          // 20000
#define IN_C 768
#define FH 8
#define FW 22
#define L 176
#define LVIS 44

#define X1_C 256
#define SX 100
#define SY 100
#define SZ 16
#define SPAT ((size_t)SX*SY*SZ)   // 160000
#define OC3 192

#define XOUT_SZ ((size_t)OC3*SPAT)

// padded split-input planes for conv3 (ic-fastest)
#define XP 102
#define YP 102
#define ZP 18

// transformer split-weight layout offsets (per layer, [N][K] hi/lo)
#define TW_OFF   0
#define TW_ATT   49152
#define TW_OUT   73728
#define TW_FF1   139264
#define TW_FF2   270336
#define TW_LAYER 401408

// ---------------- scratch ----------------
__device__ float g_full[CAMS*L*IN_C];
__device__ float g_feat[CAMS*L*D];
__device__ float g_val [CAMS*L*D];
__device__ float g_off [NQ*HEADS*CAMS*PTS*2];
__device__ float g_att [NQ*HEADS*CAMS*PTS];
__device__ float g_agg [NQ*D];
__device__ float g_q   [NQ*D];
__device__ float g_qt  [NQ*D];
__device__ float g_h1  [NQ*FFN];
__device__ float g_x1  [(size_t)X1_C*SX*SY*SZ];
__device__ u16 g_xh[(size_t)XP*YP*ZP*256];
__device__ u16 g_xl[(size_t)XP*YP*ZP*256];
__device__ u16 g_wh[27*OC3*256];
__device__ u16 g_wl[27*OC3*256];
__device__ u16 g_twh[3*TW_LAYER];
__device__ u16 g_twl[3*TW_LAYER];
__device__ u16 g_dwh[8*D*D];
__device__ u16 g_dwl[8*D*D];
__device__ double g_gnsum[32];
__device__ float  g_gnmi[32];

// ---------------- helpers ----------------
__device__ __forceinline__ uint32_t smem_u32(const void* p)
{
    uint32_t a;
    asm("{ .reg .u64 t; cvta.to.shared.u64 t, %1; cvt.u32.u64 %0, t; }" : "=r"(a) : "l"(p));
    return a;
}

__device__ __forceinline__ void split_bf16(float v, u16& h, u16& l)
{
    __nv_bfloat16 bh = __float2bfloat16(v);
    float fh = __bfloat162float(bh);
    __nv_bfloat16 bl = __float2bfloat16(v - fh);
    h = __bfloat16_as_ushort(bh);
    l = __bfloat16_as_ushort(bl);
}

__device__ __forceinline__ void mma_bf16(float* c, const unsigned* a, const unsigned* b)
{
    asm volatile(
        "mma.sync.aligned.m16n8k16.row.col.f32.bf16.bf16.f32 "
        "{%0,%1,%2,%3}, {%4,%5,%6,%7}, {%8,%9}, {%0,%1,%2,%3};\n"
        : "+f"(c[0]), "+f"(c[1]), "+f"(c[2]), "+f"(c[3])
        : "r"(a[0]), "r"(a[1]), "r"(a[2]), "r"(a[3]), "r"(b[0]), "r"(b[1]));
}

#define CP_ASYNC16(dst, src) \
    asm volatile("cp.async.cg.shared.global [%0], [%1], 16;\n" :: "r"(dst), "l"(src))
#define CP_COMMIT() asm volatile("cp.async.commit_group;\n")
#define CP_WAIT1() asm volatile("cp.async.wait_group 1;\n")
#define CP_WAIT0() asm volatile("cp.async.wait_group 0;\n")

// ---------------- restore tokens + write cam_x output ----------------
__global__ void k_restore(const float* __restrict__ camx,
                          const int* __restrict__ ids,
                          const float* __restrict__ mask_tok,
                          float* __restrict__ full,
                          float* __restrict__ camx_out)
{
    int tok = blockIdx.x;
    int n = tok / L, p = tok % L;
    int t = ids[n*L + p];
    for (int c = threadIdx.x; c < IN_C; c += blockDim.x) {
        float v = (t < LVIS) ? camx[((size_t)n*LVIS + t)*IN_C + c] : mask_tok[c];
        full[(size_t)tok*IN_C + c] = v;
        camx_out[((size_t)n*IN_C + c)*L + p] = v;
    }
}

// ---------------- fp32 tiled SGEMM (small matrices only) ----------------
// MODE: 1 +bias, 4 feat
#define TM 64
#define TN 64
#define TKK 16
template<int MODE, bool TB>
__global__ void gemm_k(const float* __restrict__ A, const float* __restrict__ B,
                       float* __restrict__ C, int M, int N, int K,
                       const float* __restrict__ bias,
                       const float* __restrict__ e1, const float* __restrict__ e2)
{
    __shared__ float As[TKK][TM+4];
    __shared__ float Bs[TKK][TN+4];
    int m0 = blockIdx.y * TM, n0 = blockIdx.x * TN;
    int t = threadIdx.x;
    int tx = t & 15, ty = t >> 4;
    float acc[4][4] = {};
    for (int k0 = 0; k0 < K; k0 += TKK) {
        for (int i = t; i < TM*TKK; i += 256) {
            int mm = i >> 4, kk = i & 15;
            int m = m0 + mm, k = k0 + kk;
            As[kk][mm] = (m < M && k < K) ? A[(size_t)m*K + k] : 0.f;
        }
        if (!TB) {
            for (int i = t; i < TKK*TN; i += 256) {
                int kk = i >> 6, nn = i & 63;
                int k = k0 + kk, n = n0 + nn;
                Bs[kk][nn] = (k < K && n < N) ? B[(size_t)k*N + n] : 0.f;
            }
        } else {
            for (int i = t; i < TKK*TN; i += 256) {
                int nn = i >> 4, kk = i & 15;
                int k = k0 + kk, n = n0 + nn;
                Bs[kk][nn] = (k < K && n < N) ? B[(size_t)n*K + k] : 0.f;
            }
        }
        __syncthreads();
        #pragma unroll
        for (int kk = 0; kk < TKK; kk++) {
            float a[4], b[4];
            #pragma unroll
            for (int i = 0; i < 4; i++) a[i] = As[kk][ty*4 + i];
            #pragma unroll
            for (int j = 0; j < 4; j++) b[j] = Bs[kk][tx*4 + j];
            #pragma unroll
            for (int i = 0; i < 4; i++)
                #pragma unroll
                for (int j = 0; j < 4; j++) acc[i][j] += a[i]*b[j];
        }
        __syncthreads();
    }
    #pragma unroll
    for (int i = 0; i < 4; i++) {
        int row = m0 + ty*4 + i;
        if (row >= M) continue;
        #pragma unroll
        for (int j = 0; j < 4; j++) {
            int col = n0 + tx*4 + j;
            if (col >= N) continue;
            float v = acc[i][j];
            if (MODE == 1) v += bias[col];
            else if (MODE == 4) {
                v += bias[col]; v = v > 0.f ? v : 0.f;
                v += e1[(row/L)*D + col] + e2[col];
            }
            C[(size_t)row*N + col] = v;
        }
    }
}

// ---------------- tensor GEMM: C = A(fp32 MxK) @ Bsplit([N][K] bf16 hi/lo) ----------------
// 3-term split. Tile 128M x 64N, 256 threads (4m x 2n warps, warp 32x32).
// MODE: 1 +bias, 2 relu(+bias), 3 +bias+res, 5 deconv scatter
template<int MODE>
__global__ void __launch_bounds__(256) tgemm(const float* __restrict__ A,
                                             const u16* __restrict__ Bh,
                                             const u16* __restrict__ Bl,
                                             float* __restrict__ C, int M, int N, int K,
                                             const float* __restrict__ bias,
                                             const float* __restrict__ res,
                                             int p1, int p2, int p3)
{
    __shared__ u16 Ah[128*40], Al[128*40], Bsh[64*40], Bsl[64*40];
    int m0 = blockIdx.y * 128, n0 = blockIdx.x * 64;
    int tid = threadIdx.x, lane = tid & 31, wrp = tid >> 5;
    int wm = wrp & 3, wn = wrp >> 2;
    int q = lane & 3, rr = lane >> 2;

    float acc[2][4][4] = {};
    const unsigned* pah = (const unsigned*)Ah;
    const unsigned* pal = (const unsigned*)Al;
    const unsigned* pbh = (const unsigned*)Bsh;
    const unsigned* pbl = (const unsigned*)Bsl;

    for (int k0 = 0; k0 < K; k0 += 32) {
        __syncthreads();
        // stage A 128x32 fp32 -> hi/lo
        #pragma unroll
        for (int it = 0; it < 16; it++) {
            int i = tid + it*256;
            int row = i >> 5, k = i & 31;
            int m = m0 + row;
            float v = (m < M) ? A[(size_t)m*K + k0 + k] : 0.f;
            u16 h, l; split_bf16(v, h, l);
            Ah[row*40 + k] = h;
            Al[row*40 + k] = l;
        }
        // stage B 64x32 hi/lo (pre-split, [N][K])
        #pragma unroll
        for (int it = 0; it < 4; it++) {
            int i = tid + it*256;
            int pl = i >> 9; int idx = i & 511;
            int n = idx >> 3, seg = idx & 7;
            uint2 v = make_uint2(0u, 0u);
            if (n0 + n < N) {
                const u16* src = (pl ? Bl : Bh) + (size_t)(n0 + n)*K + k0 + seg*4;
                v = *(const uint2*)src;
            }
            *(uint2*)((pl ? Bsl : Bsh) + n*40 + seg*4) = v;
        }
        __syncthreads();
        #pragma unroll
        for (int ks = 0; ks < 2; ks++) {
            int o = ks*8 + q;
            unsigned ah[2][4], al[2][4], bh[4][2], bl[4][2];
            #pragma unroll
            for (int mi = 0; mi < 2; mi++) {
                int ra = wm*32 + mi*16 + rr, rb = ra + 8;
                ah[mi][0] = pah[ra*20 + o]; ah[mi][1] = pah[rb*20 + o];
                ah[mi][2] = pah[ra*20 + o + 4]; ah[mi][3] = pah[rb*20 + o + 4];
                al[mi][0] = pal[ra*20 + o]; al[mi][1] = pal[rb*20 + o];
                al[mi][2] = pal[ra*20 + o + 4]; al[mi][3] = pal[rb*20 + o + 4];
            }
            #pragma unroll
            for (int nj = 0; nj < 4; nj++) {
                int n = wn*32 + nj*8 + rr;
                bh[nj][0] = pbh[n*20 + o]; bh[nj][1] = pbh[n*20 + o + 4];
                bl[nj][0] = pbl[n*20 + o]; bl[nj][1] = pbl[n*20 + o + 4];
            }
            #pragma unroll
            for (int mi = 0; mi < 2; mi++)
                #pragma unroll
                for (int nj = 0; nj < 4; nj++) {
                    mma_bf16(acc[mi][nj], ah[mi], bh[nj]);
                    mma_bf16(acc[mi][nj], ah[mi], bl[nj]);
                    mma_bf16(acc[mi][nj], al[mi], bh[nj]);
                }
        }
    }

    #pragma unroll
    for (int mi = 0; mi < 2; mi++) {
        int r0 = m0 + wm*32 + mi*16 + rr;
        #pragma unroll
        for (int nj = 0; nj < 4; nj++) {
            int col = n0 + wn*32 + nj*8 + 2*q;
            #pragma unroll
            for (int hh = 0; hh < 2; hh++) {
                int row = r0 + hh*8;
                if (row >= M) continue;
                #pragma unroll
                for (int cc = 0; cc < 2; cc++) {
                    int c = col + cc;
                    if (c >= N) continue;
                    float v = acc[mi][nj][hh*2 + cc];
                    if (MODE == 1) v += bias[c];
                    else if (MODE == 2) { v += bias[c]; v = v > 0.f ? v : 0.f; }
                    else if (MODE == 3) v += bias[c] + res[(size_t)row*N + c];
                    if (MODE == 5) {
                        int x = row % VW, y = (row / VW) % VH, z = row / (VW*VH);
                        size_t idx = (((size_t)c*SX + (2*x+p1))*SY + (2*y+p2))*SZ + (2*z+p3);
                        C[idx] = v;
                    } else {
                        C[(size_t)row*N + c] = v;
                    }
                }
            }
        }
    }
}

// ---------------- weight split: W [K][N] fp32 -> bh/bl [N][K] ----------------
__global__ void k_wsplit(const float* __restrict__ W, u16* __restrict__ bh,
                         u16* __restrict__ bl, int K, int N)
{
    int i = blockIdx.x * blockDim.x + threadIdx.x;
    if (i >= K*N) return;
    int n = i / K, k = i % K;
    u16 h, l; split_bf16(W[(size_t)k*N + n], h, l);
    bh[i] = h; bl[i] = l;
}

// deconv weights: per parity r, [N=oc][K=ic] split
__global__ void k_wdt2(const float* __restrict__ w, u16* __restrict__ dh, u16* __restrict__ dl)
{
    int i = blockIdx.x * blockDim.x + threadIdx.x;
    if (i >= 8*D*D) return;
    int ic = i & 255, o = (i >> 8) & 255, r = i >> 16;
    int r1 = (r >> 2) & 1, r2 = (r >> 1) & 1, r3 = r & 1;
    float v = w[((size_t)o*D + ic)*8 + ((1-r1)*4 + (1-r2)*2 + (1-r3))];
    u16 h, l; split_bf16(v, h, l);
    size_t idx = ((size_t)r*D + o)*D + ic;
    dh[idx] = h; dl[idx] = l;
}

// ---------------- softmax over 12 per (query, head) ----------------
__global__ void k_softmax12(float* __restrict__ att)
{
    int i = blockIdx.x * blockDim.x + threadIdx.x;
    if (i >= NQ*HEADS) return;
    float* p = att + (size_t)(i/HEADS)*(HEADS*12) + (i%HEADS)*12;
    float mx = -1e30f;
    #pragma unroll
    for (int k = 0; k < 12; k++) mx = fmaxf(mx, p[k]);
    float s = 0.f;
    float e[12];
    #pragma unroll
    for (int k = 0; k < 12; k++) { e[k] = __expf(p[k]-mx); s += e[k]; }
    float inv = 1.f/s;
    #pragma unroll
    for (int k = 0; k < 12; k++) p[k] = e[k]*inv;
}

// ---------------- bilinear sampling + aggregation ----------------
__global__ void k_sample(const float* __restrict__ off, const float* __restrict__ att,
                         const float* __restrict__ val, float* __restrict__ agg)
{
    int n = blockIdx.x;
    int t = threadIdx.x;
    __shared__ float off_s[HEADS*CAMS*PTS*2];
    __shared__ float att_s[HEADS*CAMS*PTS];
    if (t < 192) off_s[t] = off[(size_t)n*192 + t];
    if (t < 96)  att_s[t] = att[(size_t)n*96 + t];
    __syncthreads();
    int h = t >> 5, dh = t & 31;
    int qx = n % VW, qy = (n / VW) % VH;
    float refx = (qx + 0.5f) * ((float)FW / VW) - 0.5f;
    float refy = (qy + 0.5f) * ((float)FH / VH) - 0.5f;
    float acc = 0.f;
    #pragma unroll
    for (int c = 0; c < CAMS; c++) {
        #pragma unroll
        for (int p = 0; p < PTS; p++) {
            int base = ((h*CAMS + c)*PTS + p)*2;
            float x = refx + off_s[base];
            float y = refy + off_s[base+1];
            float x0f = floorf(x), y0f = floorf(y);
            float wx = x - x0f, wy = y - y0f;
            int x0 = (int)x0f, y0 = (int)y0f;
            int xc0 = min(max(x0, 0), FW-1),   xc1 = min(max(x0+1, 0), FW-1);
            int yc0 = min(max(y0, 0), FH-1),   yc1 = min(max(y0+1, 0), FH-1);
            const float* vb = val + ((size_t)c*L*HEADS + h)*DH + dh;
            float v00 = vb[(size_t)(yc0*FW + xc0)*HEADS*DH];
            float v01 = vb[(size_t)(yc0*FW + xc1)*HEADS*DH];
            float v10 = vb[(size_t)(yc1*FW + xc0)*HEADS*DH];
            float v11 = vb[(size_t)(yc1*FW + xc1)*HEADS*DH];
            float bil = (1.f-wx)*(1.f-wy)*v00 + wx*(1.f-wy)*v01
                      + (1.f-wx)*wy*v10 + wx*wy*v11;
            acc += att_s[h*12 + c*2 + p] * bil;
        }
    }
    agg[(size_t)n*D + h*DH + dh] = acc;
}

// ---------------- layernorm (row of 256) ----------------
__global__ void k_ln(const float* __restrict__ in, float* __restrict__ out,
                     const float* __restrict__ g, const float* __restrict__ b)
{
    int n = blockIdx.x, t = threadIdx.x;
    float x = in[(size_t)n*D + t];
    float s = x, s2 = x*x;
    #pragma unroll
    for (int o = 16; o; o >>= 1) {
        s  += __shfl_xor_sync(0xffffffffu, s,  o);
        s2 += __shfl_xor_sync(0xffffffffu, s2, o);
    }
    __shared__ float ws[8], ws2[8], mv[2];
    if ((t & 31) == 0) { ws[t>>5] = s; ws2[t>>5] = s2; }
    __syncthreads();
    if (t < 32) {
        float a = (t < 8) ? ws[t] : 0.f, a2 = (t < 8) ? ws2[t] : 0.f;
        #pragma unroll
        for (int o = 4; o; o >>= 1) {
            a  += __shfl_xor_sync(0xffffffffu, a,  o);
            a2 += __shfl_xor_sync(0xffffffffu, a2, o);
        }
        if (t == 0) {
            float m = a / D;
            float v = a2 / D - m*m;
            mv[0] = m; mv[1] = rsqrtf(v + 1e-5f);
        }
    }
    __syncthreads();
    out[(size_t)n*D + t] = (x - mv[0]) * mv[1] * g[t] + b[t];
}

// ---------------- group norm ----------------
__global__ void k_gn_zero(double* sums) { if (threadIdx.x < 32) sums[threadIdx.x] = 0.0; }

__global__ void k_gn_stats(const float* __restrict__ x, double* __restrict__ sums, long glen)
{
    int g = blockIdx.x;
    const float* p = x + (size_t)g * glen;
    double s = 0.0, s2 = 0.0;
    for (long i = (long)blockIdx.y*blockDim.x + threadIdx.x; i < glen;
         i += (long)gridDim.y*blockDim.x) {
        float v = p[i];
        s += v; s2 += (double)v*v;
    }
    __shared__ double sh[256], sh2[256];
    sh[threadIdx.x] = s; sh2[threadIdx.x] = s2;
    __syncthreads();
    for (int o = 128; o; o >>= 1) {
        if (threadIdx.x < o) { sh[threadIdx.x] += sh[threadIdx.x+o]; sh2[threadIdx.x] += sh2[threadIdx.x+o]; }
        __syncthreads();
    }
    if (threadIdx.x == 0) {
        atomicAdd(&sums[g*2],   sh[0]);
        atomicAdd(&sums[g*2+1], sh2[0]);
    }
}

__global__ void k_gn_fin(const double* __restrict__ sums, float* __restrict__ mi, long glen)
{
    int g = threadIdx.x;
    if (g < 16) {
        double m = sums[g*2] / (double)glen;
        double v = sums[g*2+1] / (double)glen - m*m;
        mi[g*2]   = (float)m;
        mi[g*2+1] = (float)(1.0 / sqrt(v + 1e-5));
    }
}

__global__ void k_gn_apply(float* __restrict__ x, const float* __restrict__ mi,
                           const float* __restrict__ gg, const float* __restrict__ gb,
                           int cpg, long S, long total)
{
    for (long i = (long)blockIdx.x*blockDim.x + threadIdx.x; i < total;
         i += (long)gridDim.x*blockDim.x) {
        int c = (int)(i / S);
        int grp = c / cpg;
        float v = (x[i] - mi[grp*2]) * mi[grp*2+1] * gg[c] + gb[c];
        x[i] = v > 0.f ? v : 0.f;
    }
}

// ---------------- conv3 prep: transpose to [x][y][z][ic] + bf16 hi/lo split ----------------
__global__ void k_prep2(const float* __restrict__ x1,
                        u16* __restrict__ xh, u16* __restrict__ xl)
{
    __shared__ float ts[64][65];
    int s0 = blockIdx.x * 64;
    int ic0 = blockIdx.y * 64;
    int tid = threadIdx.x;
    int col = tid & 63, r4 = tid >> 6;
    #pragma unroll
    for (int j = 0; j < 16; j++) {
        int ic = r4 + j*4;
        ts[ic][col] = x1[(size_t)(ic0+ic)*SPAT + s0 + col];
    }
    __syncthreads();
    #pragma unroll
    for (int j = 0; j < 16; j++) {
        int sp = r4 + j*4;
        int s = s0 + sp;
        int z = s & 15; int t2 = s >> 4; int y = t2 % SY; int x = t2 / SY;
        size_t base = ((size_t)((x+1)*YP + (y+1))*ZP + (z+1))*256 + ic0;
        u16 h, l; split_bf16(ts[col][sp], h, l);
        xh[base + col] = h;
        xl[base + col] = l;
    }
}

__global__ void k_wprep2(const float* __restrict__ w,
                         u16* __restrict__ wh, u16* __restrict__ wl)
{
    int i = blockIdx.x * blockDim.x + threadIdx.x;
    if (i >= 27*OC3*256) return;
    int ic = i & 255; int t = i >> 8;
    int oc = t % OC3; int tap = t / OC3;
    u16 h, l; split_bf16(w[((size_t)oc*X1_C + ic)*27 + tap], h, l);
    size_t idx = ((size_t)tap*OC3 + oc)*256 + ic;
    wh[idx] = h; wl[idx] = l;
}

// ---------------- conv3 v3: mma.sync + cp.async double-buffered weights ----------------
// Block: 2x x 4y x 16z (M=128) x 192 oc. ic chunk 32. 512 threads, 16 warps 4m x 4n.
#define CV_AHI 0
#define CV_ALO 34560
#define CV_W   69120
#define CV_WBUF 30720
#define CV_WLO 15360
#define CV_SMEM 130560

__global__ void __launch_bounds__(512) k_conv3_v3(const u16* __restrict__ xh,
                                                  const u16* __restrict__ xl,
                                                  const u16* __restrict__ wh,
                                                  const u16* __restrict__ wl,
                                                  float* __restrict__ out)
{
    extern __shared__ unsigned char sm[];
    uint32_t smb = smem_u32(sm);
    int tid = threadIdx.x, lane = tid & 31, wrp = tid >> 5;
    int wm = wrp & 3, wn = wrp >> 2;
    int q = lane & 3, rr = lane >> 2;
    int xo = wm >> 1, yb = (wm & 1) * 2;
    int x0 = blockIdx.x * 2, y0 = blockIdx.y * 4;

    float acc[2][6][4];
    #pragma unroll
    for (int f = 0; f < 2; f++)
        #pragma unroll
        for (int j = 0; j < 6; j++)
            #pragma unroll
            for (int k = 0; k < 4; k++) acc[f][j][k] = 0.f;

    const unsigned* pah = (const unsigned*)(sm + CV_AHI);
    const unsigned* pal = (const unsigned*)(sm + CV_ALO);

    for (int c = 0; c < 8; c++) {
        int ic0 = c * 32;
        // issue A chunk (432 rows x 32 ic x 2 planes)
        #pragma unroll
        for (int it = 0; it < 7; it++) {
            int i = tid + it*512;
            if (i < 3456) {
                int pl = (i >= 1728);
                int idx = pl ? i - 1728 : i;
                int row = idx >> 2, seg = idx & 3;
                int zz = row % 18; int t1 = row / 18;
                int yy = t1 % 6, xx = t1 / 6;
                const u16* src = (pl ? xl : xh)
                    + ((size_t)((x0+xx)*YP + (y0+yy))*ZP + zz)*256 + ic0 + seg*8;
                uint32_t dst = smb + (pl ? CV_ALO : CV_AHI) + row*80 + seg*16;
                CP_ASYNC16(dst, src);
            }
        }
        // issue W tap0 -> buf0, commit with A as one group
        #pragma unroll
        for (int it = 0; it < 3; it++) {
            int i = tid + it*512;
            int pl = (i >= 768);
            int idx = pl ? i - 768 : i;
            int row = idx >> 2, seg = idx & 3;
            const u16* src = (pl ? wl : wh) + ((size_t)(0*OC3 + row))*256 + ic0 + seg*8;
            uint32_t dst = smb + CV_W + pl*CV_WLO + row*80 + seg*16;
            CP_ASYNC16(dst, src);
        }
        CP_COMMIT();

        for (int tap = 0; tap < 27; tap++) {
            int cur = tap & 1;
            if (tap < 26) {
                int nb = (tap + 1) & 1;
                #pragma unroll
                for (int it = 0; it < 3; it++) {
                    int i = tid + it*512;
                    int pl = (i >= 768);
                    int idx = pl ? i - 768 : i;
                    int row = idx >> 2, seg = idx & 3;
                    const u16* src = (pl ? wl : wh)
                        + ((size_t)((tap+1)*OC3 + row))*256 + ic0 + seg*8;
                    uint32_t dst = smb + CV_W + nb*CV_WBUF + pl*CV_WLO + row*80 + seg*16;
                    CP_ASYNC16(dst, src);
                }
                CP_COMMIT();
                CP_WAIT1();
            } else {
                CP_WAIT0();
            }
            __syncthreads();

            int k1 = tap / 9, k2 = (tap / 3) % 3, k3 = tap % 3;
            const unsigned* pwh = (const unsigned*)(sm + CV_W + cur*CV_WBUF);
            const unsigned* pwl = (const unsigned*)(sm + CV_W + cur*CV_WBUF + CV_WLO);

            #pragma unroll
            for (int ks = 0; ks < 2; ks++) {
                int o = ks*8 + q;
                unsigned ah[2][4], al[2][4], bh[6][2], bl[6][2];
                #pragma unroll
                for (int f = 0; f < 2; f++) {
                    int ra = ((xo + k1)*6 + (yb + f + k2))*18 + rr + k3;
                    int rb = ra + 8;
                    ah[f][0] = pah[ra*20 + o]; ah[f][1] = pah[rb*20 + o];
                    ah[f][2] = pah[ra*20 + o + 4]; ah[f][3] = pah[rb*20 + o + 4];
                    al[f][0] = pal[ra*20 + o]; al[f][1] = pal[rb*20 + o];
                    al[f][2] = pal[ra*20 + o + 4]; al[f][3] = pal[rb*20 + o + 4];
                }
                #pragma unroll
                for (int j = 0; j < 6; j++) {
                    int n = wn*48 + j*8 + rr;
                    bh[j][0] = pwh[n*20 + o]; bh[j][1] = pwh[n*20 + o + 4];
                    bl[j][0] = pwl[n*20 + o]; bl[j][1] = pwl[n*20 + o + 4];
                }
                #pragma unroll
                for (int f = 0; f < 2; f++)
                    #pragma unroll
                    for (int j = 0; j < 6; j++) {
                        mma_bf16(acc[f][j], ah[f], bh[j]);
                        mma_bf16(acc[f][j], ah[f], bl[j]);
                        mma_bf16(acc[f][j], al[f], bh[j]);
                    }
            }
            __syncthreads();
        }
    }

    #pragma unroll
    for (int f = 0; f < 2; f++) {
        int Xg = x0 + xo, Yg = y0 + yb + f;
        #pragma unroll
        for (int j = 0; j < 6; j++) {
            int oc = wn*48 + j*8 + 2*q;
            size_t base = (((size_t)oc*SX + Xg)*SY + Yg)*SZ;
            out[base + rr]            = acc[f][j][0];
            out[base + rr + 8]        = acc[f][j][2];
            out[base + SPAT + rr]     = acc[f][j][1];
            out[base + SPAT + rr + 8] = acc[f][j][3];
        }
    }
}

// ---------------- host orchestration ----------------
extern "C" void kernel_launch(void* const* d_in, const int* in_sizes, int n_in,
                              void* d_out, int out_size)
{
    int shift = 0;
    if (n_in >= 4 && in_sizes[2] == 1 && in_sizes[3] == 1) shift = 0;
    else shift = 2;
    #define IN(i) ((i) >= 2 ? d_in[(i) - shift] : d_in[(i)])

    const float* camera_x  = (const float*)IN(0);
    const int*   ids       = (const int*)  IN(1);
    const float* mask_tok  = (const float*)IN(4);
    const float* vol_emb   = (const float*)IN(5);
    const float* W_tc      = (const float*)IN(6);
    const float* b_tc      = (const float*)IN(7);
    const float* cams_emb  = (const float*)IN(8);
    const float* lvl_emb   = (const float*)IN(9);
    const float* W_off     = (const float*)IN(10);
    const float* b_off     = (const float*)IN(11);
    const float* W_att     = (const float*)IN(12);
    const float* b_att     = (const float*)IN(13);
    const float* W_val     = (const float*)IN(14);
    const float* b_val     = (const float*)IN(15);
    const float* W_out     = (const float*)IN(16);
    const float* b_out     = (const float*)IN(17);
    const float* ln1_g     = (const float*)IN(18);
    const float* ln1_b     = (const float*)IN(19);
    const float* W_ff1     = (const float*)IN(20);
    const float* b_ff1     = (const float*)IN(21);
    const float* W_ff2     = (const float*)IN(22);
    const float* b_ff2     = (const float*)IN(23);
    const float* ln2_g     = (const float*)IN(24);
    const float* ln2_b     = (const float*)IN(25);
    const float* deconv_w  = (const float*)IN(26);
    const float* gn1_g     = (const float*)IN(27);
    const float* gn1_b     = (const float*)IN(28);
    const float* conv3_w   = (const float*)IN(29);
    const float* gn2_g     = (const float*)IN(30);
    const float* gn2_b     = (const float*)IN(31);
    #undef IN

    float* out = (float*)d_out;

    static int cfg = 0;
    if (!cfg) {
        cudaFuncSetAttribute(k_conv3_v3, cudaFuncAttributeMaxDynamicSharedMemorySize, CV_SMEM);
        cfg = 1;
    }

    float *p_full, *p_feat, *p_val, *p_off, *p_att, *p_agg, *p_q, *p_qt, *p_h1, *p_x1, *p_mi;
    u16 *p_xh, *p_xl, *p_wh, *p_wl, *p_twh, *p_twl, *p_dwh, *p_dwl;
    double* p_sum;
    cudaGetSymbolAddress((void**)&p_full, g_full);
    cudaGetSymbolAddress((void**)&p_feat, g_feat);
    cudaGetSymbolAddress((void**)&p_val,  g_val);
    cudaGetSymbolAddress((void**)&p_off,  g_off);
    cudaGetSymbolAddress((void**)&p_att,  g_att);
    cudaGetSymbolAddress((void**)&p_agg,  g_agg);
    cudaGetSymbolAddress((void**)&p_q,    g_q);
    cudaGetSymbolAddress((void**)&p_qt,   g_qt);
    cudaGetSymbolAddress((void**)&p_h1,   g_h1);
    cudaGetSymbolAddress((void**)&p_x1,   g_x1);
    cudaGetSymbolAddress((void**)&p_xh,   g_xh);
    cudaGetSymbolAddress((void**)&p_xl,   g_xl);
    cudaGetSymbolAddress((void**)&p_wh,   g_wh);
    cudaGetSymbolAddress((void**)&p_wl,   g_wl);
    cudaGetSymbolAddress((void**)&p_twh,  g_twh);
    cudaGetSymbolAddress((void**)&p_twl,  g_twl);
    cudaGetSymbolAddress((void**)&p_dwh,  g_dwh);
    cudaGetSymbolAddress((void**)&p_dwl,  g_dwl);
    cudaGetSymbolAddress((void**)&p_sum,  g_gnsum);
    cudaGetSymbolAddress((void**)&p_mi,   g_gnmi);

    // halo zeroing for conv planes
    cudaMemsetAsync(p_xh, 0, (size_t)XP*YP*ZP*256*sizeof(u16));
    cudaMemsetAsync(p_xl, 0, (size_t)XP*YP*ZP*256*sizeof(u16));

    // weight preprocessing (independent)
    k_wprep2<<<(27*OC3*256 + 255)/256, 256>>>(conv3_w, p_wh, p_wl);
    k_wdt2<<<(8*D*D + 255)/256, 256>>>(deconv_w, p_dwh, p_dwl);
    for (int l = 0; l < LAYERS; l++) {
        size_t lb = (size_t)l*TW_LAYER;
        k_wsplit<<<(256*192 + 255)/256, 256>>>(W_off + (size_t)l*D*192, p_twh + lb + TW_OFF, p_twl + lb + TW_OFF, 256, 192);
        k_wsplit<<<(256*96  + 255)/256, 256>>>(W_att + (size_t)l*D*96,  p_twh + lb + TW_ATT, p_twl + lb + TW_ATT, 256, 96);
        k_wsplit<<<(256*256 + 255)/256, 256>>>(W_out + (size_t)l*D*D,   p_twh + lb + TW_OUT, p_twl + lb + TW_OUT, 256, 256);
        k_wsplit<<<(256*512 + 255)/256, 256>>>(W_ff1 + (size_t)l*D*FFN, p_twh + lb + TW_FF1, p_twl + lb + TW_FF1, 256, 512);
        k_wsplit<<<(512*256 + 255)/256, 256>>>(W_ff2 + (size_t)l*FFN*D, p_twh + lb + TW_FF2, p_twl + lb + TW_FF2, 512, 256);
    }

    // stage A: restore + cam_x output
    k_restore<<<CAMS*L, 256>>>(camera_x, ids, mask_tok, p_full, out + XOUT_SZ);

    // stage B: feature projection (fp32; W_tc is (N,K) -> TB)
    gemm_k<4, true><<<dim3(4, 17), 256>>>(p_full, W_tc, p_feat, CAMS*L, D, IN_C,
                                          b_tc, cams_emb, lvl_emb);

    cudaMemcpyAsync(p_q, vol_emb, (size_t)NQ*D*sizeof(float), cudaMemcpyDeviceToDevice);

    const int MBT = (NQ + 127) / 128;   // 157
    for (int l = 0; l < LAYERS; l++) {
        size_t lb = (size_t)l*TW_LAYER;
        gemm_k<1, false><<<dim3(4, 17), 256>>>(p_feat, W_val + (size_t)l*D*D, p_val,
                                               CAMS*L, D, D, b_val + l*D, nullptr, nullptr);
        tgemm<1><<<dim3(3, MBT), 256>>>(p_q, p_twh + lb + TW_OFF, p_twl + lb + TW_OFF,
                                        p_off, NQ, 192, 256, b_off + l*192, nullptr, 0,0,0);
        tgemm<1><<<dim3(2, MBT), 256>>>(p_q, p_twh + lb + TW_ATT, p_twl + lb + TW_ATT,
                                        p_att, NQ, 96, 256, b_att + l*96, nullptr, 0,0,0);
        k_softmax12<<<(NQ*HEADS + 255)/256, 256>>>(p_att);
        k_sample<<<NQ, 256>>>(p_off, p_att, p_val, p_agg);
        tgemm<3><<<dim3(4, MBT), 256>>>(p_agg, p_twh + lb + TW_OUT, p_twl + lb + TW_OUT,
                                        p_qt, NQ, 256, 256, b_out + l*D, p_q, 0,0,0);
        k_ln<<<NQ, 256>>>(p_qt, p_q, ln1_g + l*D, ln1_b + l*D);
        tgemm<2><<<dim3(8, MBT), 256>>>(p_q, p_twh + lb + TW_FF1, p_twl + lb + TW_FF1,
                                        p_h1, NQ, 512, 256, b_ff1 + l*FFN, nullptr, 0,0,0);
        tgemm<3><<<dim3(4, MBT), 256>>>(p_h1, p_twh + lb + TW_FF2, p_twl + lb + TW_FF2,
                                        p_qt, NQ, 256, 512, b_ff2 + l*D, p_q, 0,0,0);
        k_ln<<<NQ, 256>>>(p_qt, p_q, ln2_g + l*D, ln2_b + l*D);
    }

    // deconv as 8 parity tensor GEMMs (scatter epilogue)
    for (int r = 0; r < 8; r++) {
        tgemm<5><<<dim3(4, MBT), 256>>>(p_q, p_dwh + (size_t)r*D*D, p_dwl + (size_t)r*D*D,
                                        p_x1, NQ, 256, 256, nullptr, nullptr,
                                        (r >> 2) & 1, (r >> 1) & 1, r & 1);
    }

    // group norm 1 + relu
    {
        long glen = 16L * (long)SPAT;
        k_gn_zero<<<1, 32>>>(p_sum);
        k_gn_stats<<<dim3(16, 64), 256>>>(p_x1, p_sum, glen);
        k_gn_fin<<<1, 32>>>(p_sum, p_mi, glen);
        k_gn_apply<<<4096, 256>>>(p_x1, p_mi, gn1_g, gn1_b, 16, (long)SPAT, (long)X1_C*SPAT);
    }

    // conv3 input prep
    k_prep2<<<dim3(2500, 4), 256>>>(p_x1, p_xh, p_xl);

    // conv3 via mma.sync v3
    k_conv3_v3<<<dim3(SX/2, SY/4), 512, CV_SMEM>>>(p_xh, p_xl, p_wh, p_wl, out);

    // group norm 2 + relu
    {
        long glen = 12L * (long)SPAT;
        k_gn_zero<<<1, 32>>>(p_sum);
        k_gn_stats<<<dim3(16, 64), 256>>>(out, p_sum, glen);
        k_gn_fin<<<1, 32>>>(p_sum, p_mi, glen);
        k_gn_apply<<<4096, 256>>>(out, p_mi, gn2_g, gn2_b, 12, (long)SPAT, (long)OC3*SPAT);
    }
}

// round 7
// speedup vs baseline: 3.2689x; 1.2496x over previous
#include <cuda_runtime.h>
#include <cuda_bf16.h>
#include <cuda_fp16.h>
#include <cstddef>
#include <cstdint>

typedef unsigned short u16;

// ---------------- problem constants ----------------
#define CAMS 6
#define HEADS 8
#define PTS 2
#define LAYERS 3
#define D 256
#define DH 32
#define FFN 512
#define VZ 8
#define VH 50
#define VW 50
#define NQ (VZ*VH*VW)          // 20000
#define IN_C 768
#define FH 8
#define FW 22
#define L 176
#define LVIS 44

#define X1_C 256
#define SX 100
#define SY 100
#define SZ 16
#define SPAT ((size_t)SX*SY*SZ)   // 160000
#define OC3 192

#define XOUT_SZ ((size_t)OC3*SPAT)

// padded split-input planes for conv3 (ic-fastest)
#define XP 102
#define YP 102
#define ZP 18

// transformer split-weight layout offsets (per layer, [N][K] hi/lo)
#define TW_OFF   0
#define TW_ATT   49152
#define TW_OUT   73728
#define TW_FF1   139264
#define TW_FF2   270336
#define TW_LAYER 401408

// ---------------- scratch ----------------
__device__ float g_full[CAMS*L*IN_C];
__device__ float g_feat[CAMS*L*D];
__device__ float g_val [CAMS*L*D];
__device__ float g_off [NQ*HEADS*CAMS*PTS*2];
__device__ float g_att [NQ*HEADS*CAMS*PTS];
__device__ float g_agg [NQ*D];
__device__ float g_q   [NQ*D];
__device__ float g_qt  [NQ*D];
__device__ float g_h1  [NQ*FFN];
__device__ float g_x1  [(size_t)X1_C*SX*SY*SZ];
__device__ u16 g_xh[(size_t)XP*YP*ZP*256];      // fp16 hi plane
__device__ u16 g_xl[(size_t)XP*YP*ZP*256];      // fp16 lo plane
__device__ u16 g_wh[27*OC3*256];                // fp16 conv weights [tap][oc][ic]
__device__ u16 g_twh[3*TW_LAYER];
__device__ u16 g_twl[3*TW_LAYER];
__device__ u16 g_dwh[8*D*D];
__device__ u16 g_dwl[8*D*D];
__device__ double g_gnsum[32];
__device__ float  g_gnmi[32];

// ---------------- helpers ----------------
__device__ __forceinline__ uint32_t smem_u32(const void* p)
{
    uint32_t a;
    asm("{ .reg .u64 t; cvta.to.shared.u64 t, %1; cvt.u32.u64 %0, t; }" : "=r"(a) : "l"(p));
    return a;
}

__device__ __forceinline__ void split_bf16(float v, u16& h, u16& l)
{
    __nv_bfloat16 bh = __float2bfloat16(v);
    float fh = __bfloat162float(bh);
    __nv_bfloat16 bl = __float2bfloat16(v - fh);
    h = __bfloat16_as_ushort(bh);
    l = __bfloat16_as_ushort(bl);
}

__device__ __forceinline__ void split_fp16(float v, u16& h, u16& l)
{
    __half hh = __float2half_rn(v);
    float fh = __half2float(hh);
    __half ll = __float2half_rn(v - fh);
    h = __half_as_ushort(hh);
    l = __half_as_ushort(ll);
}

__device__ __forceinline__ void mma_bf16(float* c, const unsigned* a, const unsigned* b)
{
    asm volatile(
        "mma.sync.aligned.m16n8k16.row.col.f32.bf16.bf16.f32 "
        "{%0,%1,%2,%3}, {%4,%5,%6,%7}, {%8,%9}, {%0,%1,%2,%3};\n"
        : "+f"(c[0]), "+f"(c[1]), "+f"(c[2]), "+f"(c[3])
        : "r"(a[0]), "r"(a[1]), "r"(a[2]), "r"(a[3]), "r"(b[0]), "r"(b[1]));
}

__device__ __forceinline__ void mma_fp16(float* c, const unsigned* a, const unsigned* b)
{
    asm volatile(
        "mma.sync.aligned.m16n8k16.row.col.f32.f16.f16.f32 "
        "{%0,%1,%2,%3}, {%4,%5,%6,%7}, {%8,%9}, {%0,%1,%2,%3};\n"
        : "+f"(c[0]), "+f"(c[1]), "+f"(c[2]), "+f"(c[3])
        : "r"(a[0]), "r"(a[1]), "r"(a[2]), "r"(a[3]), "r"(b[0]), "r"(b[1]));
}

#define CP_ASYNC16(dst, src) \
    asm volatile("cp.async.cg.shared.global [%0], [%1], 16;\n" :: "r"(dst), "l"(src))
#define CP_COMMIT() asm volatile("cp.async.commit_group;\n")
#define CP_WAIT1() asm volatile("cp.async.wait_group 1;\n")
#define CP_WAIT0() asm volatile("cp.async.wait_group 0;\n")

// ---------------- restore tokens + write cam_x output ----------------
__global__ void k_restore(const float* __restrict__ camx,
                          const int* __restrict__ ids,
                          const float* __restrict__ mask_tok,
                          float* __restrict__ full,
                          float* __restrict__ camx_out)
{
    int tok = blockIdx.x;
    int n = tok / L, p = tok % L;
    int t = ids[n*L + p];
    for (int c = threadIdx.x; c < IN_C; c += blockDim.x) {
        float v = (t < LVIS) ? camx[((size_t)n*LVIS + t)*IN_C + c] : mask_tok[c];
        full[(size_t)tok*IN_C + c] = v;
        camx_out[((size_t)n*IN_C + c)*L + p] = v;
    }
}

// ---------------- fp32 tiled SGEMM (small matrices only) ----------------
// MODE: 1 +bias, 4 feat
#define TM 64
#define TN 64
#define TKK 16
template<int MODE, bool TB>
__global__ void gemm_k(const float* __restrict__ A, const float* __restrict__ B,
                       float* __restrict__ C, int M, int N, int K,
                       const float* __restrict__ bias,
                       const float* __restrict__ e1, const float* __restrict__ e2)
{
    __shared__ float As[TKK][TM+4];
    __shared__ float Bs[TKK][TN+4];
    int m0 = blockIdx.y * TM, n0 = blockIdx.x * TN;
    int t = threadIdx.x;
    int tx = t & 15, ty = t >> 4;
    float acc[4][4] = {};
    for (int k0 = 0; k0 < K; k0 += TKK) {
        for (int i = t; i < TM*TKK; i += 256) {
            int mm = i >> 4, kk = i & 15;
            int m = m0 + mm, k = k0 + kk;
            As[kk][mm] = (m < M && k < K) ? A[(size_t)m*K + k] : 0.f;
        }
        if (!TB) {
            for (int i = t; i < TKK*TN; i += 256) {
                int kk = i >> 6, nn = i & 63;
                int k = k0 + kk, n = n0 + nn;
                Bs[kk][nn] = (k < K && n < N) ? B[(size_t)k*N + n] : 0.f;
            }
        } else {
            for (int i = t; i < TKK*TN; i += 256) {
                int nn = i >> 4, kk = i & 15;
                int k = k0 + kk, n = n0 + nn;
                Bs[kk][nn] = (k < K && n < N) ? B[(size_t)n*K + k] : 0.f;
            }
        }
        __syncthreads();
        #pragma unroll
        for (int kk = 0; kk < TKK; kk++) {
            float a[4], b[4];
            #pragma unroll
            for (int i = 0; i < 4; i++) a[i] = As[kk][ty*4 + i];
            #pragma unroll
            for (int j = 0; j < 4; j++) b[j] = Bs[kk][tx*4 + j];
            #pragma unroll
            for (int i = 0; i < 4; i++)
                #pragma unroll
                for (int j = 0; j < 4; j++) acc[i][j] += a[i]*b[j];
        }
        __syncthreads();
    }
    #pragma unroll
    for (int i = 0; i < 4; i++) {
        int row = m0 + ty*4 + i;
        if (row >= M) continue;
        #pragma unroll
        for (int j = 0; j < 4; j++) {
            int col = n0 + tx*4 + j;
            if (col >= N) continue;
            float v = acc[i][j];
            if (MODE == 1) v += bias[col];
            else if (MODE == 4) {
                v += bias[col]; v = v > 0.f ? v : 0.f;
                v += e1[(row/L)*D + col] + e2[col];
            }
            C[(size_t)row*N + col] = v;
        }
    }
}

// ---------------- tensor GEMM: C = A(fp32 MxK) @ Bsplit([N][K] bf16 hi/lo) ----------------
// 3-term bf16 split. Tile 128M x 64N, 256 threads.
// MODE: 1 +bias, 2 relu(+bias), 3 +bias+res, 5 deconv scatter
template<int MODE>
__global__ void __launch_bounds__(256) tgemm(const float* __restrict__ A,
                                             const u16* __restrict__ Bh,
                                             const u16* __restrict__ Bl,
                                             float* __restrict__ C, int M, int N, int K,
                                             const float* __restrict__ bias,
                                             const float* __restrict__ res,
                                             int p1, int p2, int p3)
{
    __shared__ u16 Ah[128*40], Al[128*40], Bsh[64*40], Bsl[64*40];
    int m0 = blockIdx.y * 128, n0 = blockIdx.x * 64;
    int tid = threadIdx.x, lane = tid & 31, wrp = tid >> 5;
    int wm = wrp & 3, wn = wrp >> 2;
    int q = lane & 3, rr = lane >> 2;

    float acc[2][4][4] = {};
    const unsigned* pah = (const unsigned*)Ah;
    const unsigned* pal = (const unsigned*)Al;
    const unsigned* pbh = (const unsigned*)Bsh;
    const unsigned* pbl = (const unsigned*)Bsl;

    for (int k0 = 0; k0 < K; k0 += 32) {
        __syncthreads();
        #pragma unroll
        for (int it = 0; it < 16; it++) {
            int i = tid + it*256;
            int row = i >> 5, k = i & 31;
            int m = m0 + row;
            float v = (m < M) ? A[(size_t)m*K + k0 + k] : 0.f;
            u16 h, l; split_bf16(v, h, l);
            Ah[row*40 + k] = h;
            Al[row*40 + k] = l;
        }
        #pragma unroll
        for (int it = 0; it < 4; it++) {
            int i = tid + it*256;
            int pl = i >> 9; int idx = i & 511;
            int n = idx >> 3, seg = idx & 7;
            uint2 v = make_uint2(0u, 0u);
            if (n0 + n < N) {
                const u16* src = (pl ? Bl : Bh) + (size_t)(n0 + n)*K + k0 + seg*4;
                v = *(const uint2*)src;
            }
            *(uint2*)((pl ? Bsl : Bsh) + n*40 + seg*4) = v;
        }
        __syncthreads();
        #pragma unroll
        for (int ks = 0; ks < 2; ks++) {
            int o = ks*8 + q;
            unsigned ah[2][4], al[2][4], bh[4][2], bl[4][2];
            #pragma unroll
            for (int mi = 0; mi < 2; mi++) {
                int ra = wm*32 + mi*16 + rr, rb = ra + 8;
                ah[mi][0] = pah[ra*20 + o]; ah[mi][1] = pah[rb*20 + o];
                ah[mi][2] = pah[ra*20 + o + 4]; ah[mi][3] = pah[rb*20 + o + 4];
                al[mi][0] = pal[ra*20 + o]; al[mi][1] = pal[rb*20 + o];
                al[mi][2] = pal[ra*20 + o + 4]; al[mi][3] = pal[rb*20 + o + 4];
            }
            #pragma unroll
            for (int nj = 0; nj < 4; nj++) {
                int n = wn*32 + nj*8 + rr;
                bh[nj][0] = pbh[n*20 + o]; bh[nj][1] = pbh[n*20 + o + 4];
                bl[nj][0] = pbl[n*20 + o]; bl[nj][1] = pbl[n*20 + o + 4];
            }
            #pragma unroll
            for (int mi = 0; mi < 2; mi++)
                #pragma unroll
                for (int nj = 0; nj < 4; nj++) {
                    mma_bf16(acc[mi][nj], ah[mi], bh[nj]);
                    mma_bf16(acc[mi][nj], ah[mi], bl[nj]);
                    mma_bf16(acc[mi][nj], al[mi], bh[nj]);
                }
        }
    }

    #pragma unroll
    for (int mi = 0; mi < 2; mi++) {
        int r0 = m0 + wm*32 + mi*16 + rr;
        #pragma unroll
        for (int nj = 0; nj < 4; nj++) {
            int col = n0 + wn*32 + nj*8 + 2*q;
            #pragma unroll
            for (int hh = 0; hh < 2; hh++) {
                int row = r0 + hh*8;
                if (row >= M) continue;
                #pragma unroll
                for (int cc = 0; cc < 2; cc++) {
                    int c = col + cc;
                    if (c >= N) continue;
                    float v = acc[mi][nj][hh*2 + cc];
                    if (MODE == 1) v += bias[c];
                    else if (MODE == 2) { v += bias[c]; v = v > 0.f ? v : 0.f; }
                    else if (MODE == 3) v += bias[c] + res[(size_t)row*N + c];
                    if (MODE == 5) {
                        int x = row % VW, y = (row / VW) % VH, z = row / (VW*VH);
                        size_t idx = (((size_t)c*SX + (2*x+p1))*SY + (2*y+p2))*SZ + (2*z+p3);
                        C[idx] = v;
                    } else {
                        C[(size_t)row*N + c] = v;
                    }
                }
            }
        }
    }
}

// ---------------- weight split: W [K][N] fp32 -> bh/bl [N][K] (bf16) ----------------
__global__ void k_wsplit(const float* __restrict__ W, u16* __restrict__ bh,
                         u16* __restrict__ bl, int K, int N)
{
    int i = blockIdx.x * blockDim.x + threadIdx.x;
    if (i >= K*N) return;
    int n = i / K, k = i % K;
    u16 h, l; split_bf16(W[(size_t)k*N + n], h, l);
    bh[i] = h; bl[i] = l;
}

// deconv weights: per parity r, [N=oc][K=ic] bf16 split
__global__ void k_wdt2(const float* __restrict__ w, u16* __restrict__ dh, u16* __restrict__ dl)
{
    int i = blockIdx.x * blockDim.x + threadIdx.x;
    if (i >= 8*D*D) return;
    int ic = i & 255, o = (i >> 8) & 255, r = i >> 16;
    int r1 = (r >> 2) & 1, r2 = (r >> 1) & 1, r3 = r & 1;
    float v = w[((size_t)o*D + ic)*8 + ((1-r1)*4 + (1-r2)*2 + (1-r3))];
    u16 h, l; split_bf16(v, h, l);
    size_t idx = ((size_t)r*D + o)*D + ic;
    dh[idx] = h; dl[idx] = l;
}

// ---------------- softmax over 12 per (query, head) ----------------
__global__ void k_softmax12(float* __restrict__ att)
{
    int i = blockIdx.x * blockDim.x + threadIdx.x;
    if (i >= NQ*HEADS) return;
    float* p = att + (size_t)(i/HEADS)*(HEADS*12) + (i%HEADS)*12;
    float mx = -1e30f;
    #pragma unroll
    for (int k = 0; k < 12; k++) mx = fmaxf(mx, p[k]);
    float s = 0.f;
    float e[12];
    #pragma unroll
    for (int k = 0; k < 12; k++) { e[k] = __expf(p[k]-mx); s += e[k]; }
    float inv = 1.f/s;
    #pragma unroll
    for (int k = 0; k < 12; k++) p[k] = e[k]*inv;
}

// ---------------- bilinear sampling + aggregation ----------------
__global__ void k_sample(const float* __restrict__ off, const float* __restrict__ att,
                         const float* __restrict__ val, float* __restrict__ agg)
{
    int n = blockIdx.x;
    int t = threadIdx.x;
    __shared__ float off_s[HEADS*CAMS*PTS*2];
    __shared__ float att_s[HEADS*CAMS*PTS];
    if (t < 192) off_s[t] = off[(size_t)n*192 + t];
    if (t < 96)  att_s[t] = att[(size_t)n*96 + t];
    __syncthreads();
    int h = t >> 5, dh = t & 31;
    int qx = n % VW, qy = (n / VW) % VH;
    float refx = (qx + 0.5f) * ((float)FW / VW) - 0.5f;
    float refy = (qy + 0.5f) * ((float)FH / VH) - 0.5f;
    float acc = 0.f;
    #pragma unroll
    for (int c = 0; c < CAMS; c++) {
        #pragma unroll
        for (int p = 0; p < PTS; p++) {
            int base = ((h*CAMS + c)*PTS + p)*2;
            float x = refx + off_s[base];
            float y = refy + off_s[base+1];
            float x0f = floorf(x), y0f = floorf(y);
            float wx = x - x0f, wy = y - y0f;
            int x0 = (int)x0f, y0 = (int)y0f;
            int xc0 = min(max(x0, 0), FW-1),   xc1 = min(max(x0+1, 0), FW-1);
            int yc0 = min(max(y0, 0), FH-1),   yc1 = min(max(y0+1, 0), FH-1);
            const float* vb = val + ((size_t)c*L*HEADS + h)*DH + dh;
            float v00 = vb[(size_t)(yc0*FW + xc0)*HEADS*DH];
            float v01 = vb[(size_t)(yc0*FW + xc1)*HEADS*DH];
            float v10 = vb[(size_t)(yc1*FW + xc0)*HEADS*DH];
            float v11 = vb[(size_t)(yc1*FW + xc1)*HEADS*DH];
            float bil = (1.f-wx)*(1.f-wy)*v00 + wx*(1.f-wy)*v01
                      + (1.f-wx)*wy*v10 + wx*wy*v11;
            acc += att_s[h*12 + c*2 + p] * bil;
        }
    }
    agg[(size_t)n*D + h*DH + dh] = acc;
}

// ---------------- layernorm (row of 256) ----------------
__global__ void k_ln(const float* __restrict__ in, float* __restrict__ out,
                     const float* __restrict__ g, const float* __restrict__ b)
{
    int n = blockIdx.x, t = threadIdx.x;
    float x = in[(size_t)n*D + t];
    float s = x, s2 = x*x;
    #pragma unroll
    for (int o = 16; o; o >>= 1) {
        s  += __shfl_xor_sync(0xffffffffu, s,  o);
        s2 += __shfl_xor_sync(0xffffffffu, s2, o);
    }
    __shared__ float ws[8], ws2[8], mv[2];
    if ((t & 31) == 0) { ws[t>>5] = s; ws2[t>>5] = s2; }
    __syncthreads();
    if (t < 32) {
        float a = (t < 8) ? ws[t] : 0.f, a2 = (t < 8) ? ws2[t] : 0.f;
        #pragma unroll
        for (int o = 4; o; o >>= 1) {
            a  += __shfl_xor_sync(0xffffffffu, a,  o);
            a2 += __shfl_xor_sync(0xffffffffu, a2, o);
        }
        if (t == 0) {
            float m = a / D;
            float v = a2 / D - m*m;
            mv[0] = m; mv[1] = rsqrtf(v + 1e-5f);
        }
    }
    __syncthreads();
    out[(size_t)n*D + t] = (x - mv[0]) * mv[1] * g[t] + b[t];
}

// ---------------- group norm ----------------
__global__ void k_gn_zero(double* sums) { if (threadIdx.x < 32) sums[threadIdx.x] = 0.0; }

__global__ void k_gn_stats(const float* __restrict__ x, double* __restrict__ sums, long glen)
{
    int g = blockIdx.x;
    const float* p = x + (size_t)g * glen;
    double s = 0.0, s2 = 0.0;
    for (long i = (long)blockIdx.y*blockDim.x + threadIdx.x; i < glen;
         i += (long)gridDim.y*blockDim.x) {
        float v = p[i];
        s += v; s2 += (double)v*v;
    }
    __shared__ double sh[256], sh2[256];
    sh[threadIdx.x] = s; sh2[threadIdx.x] = s2;
    __syncthreads();
    for (int o = 128; o; o >>= 1) {
        if (threadIdx.x < o) { sh[threadIdx.x] += sh[threadIdx.x+o]; sh2[threadIdx.x] += sh2[threadIdx.x+o]; }
        __syncthreads();
    }
    if (threadIdx.x == 0) {
        atomicAdd(&sums[g*2],   sh[0]);
        atomicAdd(&sums[g*2+1], sh2[0]);
    }
}

__global__ void k_gn_fin(const double* __restrict__ sums, float* __restrict__ mi, long glen)
{
    int g = threadIdx.x;
    if (g < 16) {
        double m = sums[g*2] / (double)glen;
        double v = sums[g*2+1] / (double)glen - m*m;
        mi[g*2]   = (float)m;
        mi[g*2+1] = (float)(1.0 / sqrt(v + 1e-5));
    }
}

__global__ void k_gn_apply(float* __restrict__ x, const float* __restrict__ mi,
                           const float* __restrict__ gg, const float* __restrict__ gb,
                           int cpg, long S, long total)
{
    for (long i = (long)blockIdx.x*blockDim.x + threadIdx.x; i < total;
         i += (long)gridDim.x*blockDim.x) {
        int c = (int)(i / S);
        int grp = c / cpg;
        float v = (x[i] - mi[grp*2]) * mi[grp*2+1] * gg[c] + gb[c];
        x[i] = v > 0.f ? v : 0.f;
    }
}

// ---------------- fused GN1 apply + transpose + fp16 split into padded planes ----------------
__global__ void k_prep_gn(const float* __restrict__ x1, const float* __restrict__ mi,
                          const float* __restrict__ gg, const float* __restrict__ gb,
                          u16* __restrict__ xh, u16* __restrict__ xl)
{
    __shared__ float ts[64][65];
    int s0 = blockIdx.x * 64;
    int ic0 = blockIdx.y * 64;
    int tid = threadIdx.x;
    int col = tid & 63, r4 = tid >> 6;
    #pragma unroll
    for (int j = 0; j < 16; j++) {
        int ic = r4 + j*4;
        ts[ic][col] = x1[(size_t)(ic0+ic)*SPAT + s0 + col];
    }
    __syncthreads();
    int c = ic0 + col;               // channel for second phase
    int grp = c >> 4;                // GN1: 16 channels per group
    float m = mi[grp*2], inv = mi[grp*2+1];
    float gc = gg[c], bc = gb[c];
    #pragma unroll
    for (int j = 0; j < 16; j++) {
        int sp = r4 + j*4;
        int s = s0 + sp;
        int z = s & 15; int t2 = s >> 4; int y = t2 % SY; int x = t2 / SY;
        size_t base = ((size_t)((x+1)*YP + (y+1))*ZP + (z+1))*256 + ic0;
        float v = (ts[col][sp] - m) * inv * gc + bc;
        v = v > 0.f ? v : 0.f;
        u16 h, l; split_fp16(v, h, l);
        xh[base + col] = h;
        xl[base + col] = l;
    }
}

__global__ void k_wprep2(const float* __restrict__ w, u16* __restrict__ wh)
{
    int i = blockIdx.x * blockDim.x + threadIdx.x;
    if (i >= 27*OC3*256) return;
    int ic = i & 255; int t = i >> 8;
    int oc = t % OC3; int tap = t / OC3;
    wh[((size_t)tap*OC3 + oc)*256 + ic] =
        __half_as_ushort(__float2half_rn(w[((size_t)oc*X1_C + ic)*27 + tap]));
}

// ---------------- conv3 v4: fp16 2-term, cp.async double-buffered weights ----------------
// Block: 2x x 4y x 16z (M=128) x 192 oc. ic chunk 32. 512 threads, 16 warps 4m x 4n.
#define CV_AHI 0
#define CV_ALO 34560
#define CV_W   69120
#define CV_WBUF 15360
#define CV_SMEM 99840

__global__ void __launch_bounds__(512) k_conv3_v4(const u16* __restrict__ xh,
                                                  const u16* __restrict__ xl,
                                                  const u16* __restrict__ wh,
                                                  float* __restrict__ out)
{
    extern __shared__ unsigned char sm[];
    uint32_t smb = smem_u32(sm);
    int tid = threadIdx.x, lane = tid & 31, wrp = tid >> 5;
    int wm = wrp & 3, wn = wrp >> 2;
    int q = lane & 3, rr = lane >> 2;
    int xo = wm >> 1, yb = (wm & 1) * 2;
    int x0 = blockIdx.x * 2, y0 = blockIdx.y * 4;

    float acc[2][6][4];
    #pragma unroll
    for (int f = 0; f < 2; f++)
        #pragma unroll
        for (int j = 0; j < 6; j++)
            #pragma unroll
            for (int k = 0; k < 4; k++) acc[f][j][k] = 0.f;

    const unsigned* pah = (const unsigned*)(sm + CV_AHI);
    const unsigned* pal = (const unsigned*)(sm + CV_ALO);

    for (int c = 0; c < 8; c++) {
        int ic0 = c * 32;
        // issue A chunk (432 rows x 32 ic x 2 planes) -> 3456 cp.async
        #pragma unroll
        for (int it = 0; it < 7; it++) {
            int i = tid + it*512;
            if (i < 3456) {
                int pl = (i >= 1728);
                int idx = pl ? i - 1728 : i;
                int row = idx >> 2, seg = idx & 3;
                int zz = row % 18; int t1 = row / 18;
                int yy = t1 % 6, xx = t1 / 6;
                const u16* src = (pl ? xl : xh)
                    + ((size_t)((x0+xx)*YP + (y0+yy))*ZP + zz)*256 + ic0 + seg*8;
                uint32_t dst = smb + (pl ? CV_ALO : CV_AHI) + row*80 + seg*16;
                CP_ASYNC16(dst, src);
            }
        }
        // issue W tap0 -> buf0 (192 rows x 32 ic) -> 768 cp.async
        #pragma unroll
        for (int it = 0; it < 2; it++) {
            int i = tid + it*512;
            if (i < 768) {
                int row = i >> 2, seg = i & 3;
                const u16* src = wh + ((size_t)(0*OC3 + row))*256 + ic0 + seg*8;
                uint32_t dst = smb + CV_W + row*80 + seg*16;
                CP_ASYNC16(dst, src);
            }
        }
        CP_COMMIT();

        for (int tap = 0; tap < 27; tap++) {
            int cur = tap & 1;
            if (tap < 26) {
                int nb = (tap + 1) & 1;
                #pragma unroll
                for (int it = 0; it < 2; it++) {
                    int i = tid + it*512;
                    if (i < 768) {
                        int row = i >> 2, seg = i & 3;
                        const u16* src = wh + ((size_t)((tap+1)*OC3 + row))*256 + ic0 + seg*8;
                        uint32_t dst = smb + CV_W + nb*CV_WBUF + row*80 + seg*16;
                        CP_ASYNC16(dst, src);
                    }
                }
                CP_COMMIT();
                CP_WAIT1();
            } else {
                CP_WAIT0();
            }
            __syncthreads();

            int k1 = tap / 9, k2 = (tap / 3) % 3, k3 = tap % 3;
            const unsigned* pw = (const unsigned*)(sm + CV_W + cur*CV_WBUF);

            #pragma unroll
            for (int ks = 0; ks < 2; ks++) {
                int o = ks*8 + q;
                unsigned ah[2][4], al[2][4], b[6][2];
                #pragma unroll
                for (int f = 0; f < 2; f++) {
                    int ra = ((xo + k1)*6 + (yb + f + k2))*18 + rr + k3;
                    int rb = ra + 8;
                    ah[f][0] = pah[ra*20 + o]; ah[f][1] = pah[rb*20 + o];
                    ah[f][2] = pah[ra*20 + o + 4]; ah[f][3] = pah[rb*20 + o + 4];
                    al[f][0] = pal[ra*20 + o]; al[f][1] = pal[rb*20 + o];
                    al[f][2] = pal[ra*20 + o + 4]; al[f][3] = pal[rb*20 + o + 4];
                }
                #pragma unroll
                for (int j = 0; j < 6; j++) {
                    int n = wn*48 + j*8 + rr;
                    b[j][0] = pw[n*20 + o]; b[j][1] = pw[n*20 + o + 4];
                }
                #pragma unroll
                for (int f = 0; f < 2; f++)
                    #pragma unroll
                    for (int j = 0; j < 6; j++) {
                        mma_fp16(acc[f][j], ah[f], b[j]);
                        mma_fp16(acc[f][j], al[f], b[j]);
                    }
            }
            __syncthreads();
        }
    }

    #pragma unroll
    for (int f = 0; f < 2; f++) {
        int Xg = x0 + xo, Yg = y0 + yb + f;
        #pragma unroll
        for (int j = 0; j < 6; j++) {
            int oc = wn*48 + j*8 + 2*q;
            size_t base = (((size_t)oc*SX + Xg)*SY + Yg)*SZ;
            out[base + rr]            = acc[f][j][0];
            out[base + rr + 8]        = acc[f][j][2];
            out[base + SPAT + rr]     = acc[f][j][1];
            out[base + SPAT + rr + 8] = acc[f][j][3];
        }
    }
}

// ---------------- host orchestration ----------------
extern "C" void kernel_launch(void* const* d_in, const int* in_sizes, int n_in,
                              void* d_out, int out_size)
{
    int shift = 0;
    if (n_in >= 4 && in_sizes[2] == 1 && in_sizes[3] == 1) shift = 0;
    else shift = 2;
    #define IN(i) ((i) >= 2 ? d_in[(i) - shift] : d_in[(i)])

    const float* camera_x  = (const float*)IN(0);
    const int*   ids       = (const int*)  IN(1);
    const float* mask_tok  = (const float*)IN(4);
    const float* vol_emb   = (const float*)IN(5);
    const float* W_tc      = (const float*)IN(6);
    const float* b_tc      = (const float*)IN(7);
    const float* cams_emb  = (const float*)IN(8);
    const float* lvl_emb   = (const float*)IN(9);
    const float* W_off     = (const float*)IN(10);
    const float* b_off     = (const float*)IN(11);
    const float* W_att     = (const float*)IN(12);
    const float* b_att     = (const float*)IN(13);
    const float* W_val     = (const float*)IN(14);
    const float* b_val     = (const float*)IN(15);
    const float* W_out     = (const float*)IN(16);
    const float* b_out     = (const float*)IN(17);
    const float* ln1_g     = (const float*)IN(18);
    const float* ln1_b     = (const float*)IN(19);
    const float* W_ff1     = (const float*)IN(20);
    const float* b_ff1     = (const float*)IN(21);
    const float* W_ff2     = (const float*)IN(22);
    const float* b_ff2     = (const float*)IN(23);
    const float* ln2_g     = (const float*)IN(24);
    const float* ln2_b     = (const float*)IN(25);
    const float* deconv_w  = (const float*)IN(26);
    const float* gn1_g     = (const float*)IN(27);
    const float* gn1_b     = (const float*)IN(28);
    const float* conv3_w   = (const float*)IN(29);
    const float* gn2_g     = (const float*)IN(30);
    const float* gn2_b     = (const float*)IN(31);
    #undef IN

    float* out = (float*)d_out;

    static int cfg = 0;
    if (!cfg) {
        cudaFuncSetAttribute(k_conv3_v4, cudaFuncAttributeMaxDynamicSharedMemorySize, CV_SMEM);
        cfg = 1;
    }

    float *p_full, *p_feat, *p_val, *p_off, *p_att, *p_agg, *p_q, *p_qt, *p_h1, *p_x1, *p_mi;
    u16 *p_xh, *p_xl, *p_wh, *p_twh, *p_twl, *p_dwh, *p_dwl;
    double* p_sum;
    cudaGetSymbolAddress((void**)&p_full, g_full);
    cudaGetSymbolAddress((void**)&p_feat, g_feat);
    cudaGetSymbolAddress((void**)&p_val,  g_val);
    cudaGetSymbolAddress((void**)&p_off,  g_off);
    cudaGetSymbolAddress((void**)&p_att,  g_att);
    cudaGetSymbolAddress((void**)&p_agg,  g_agg);
    cudaGetSymbolAddress((void**)&p_q,    g_q);
    cudaGetSymbolAddress((void**)&p_qt,   g_qt);
    cudaGetSymbolAddress((void**)&p_h1,   g_h1);
    cudaGetSymbolAddress((void**)&p_x1,   g_x1);
    cudaGetSymbolAddress((void**)&p_xh,   g_xh);
    cudaGetSymbolAddress((void**)&p_xl,   g_xl);
    cudaGetSymbolAddress((void**)&p_wh,   g_wh);
    cudaGetSymbolAddress((void**)&p_twh,  g_twh);
    cudaGetSymbolAddress((void**)&p_twl,  g_twl);
    cudaGetSymbolAddress((void**)&p_dwh,  g_dwh);
    cudaGetSymbolAddress((void**)&p_dwl,  g_dwl);
    cudaGetSymbolAddress((void**)&p_sum,  g_gnsum);
    cudaGetSymbolAddress((void**)&p_mi,   g_gnmi);

    // halo zeroing for conv planes
    cudaMemsetAsync(p_xh, 0, (size_t)XP*YP*ZP*256*sizeof(u16));
    cudaMemsetAsync(p_xl, 0, (size_t)XP*YP*ZP*256*sizeof(u16));

    // weight preprocessing (independent)
    k_wprep2<<<(27*OC3*256 + 255)/256, 256>>>(conv3_w, p_wh);
    k_wdt2<<<(8*D*D + 255)/256, 256>>>(deconv_w, p_dwh, p_dwl);
    for (int l = 0; l < LAYERS; l++) {
        size_t lb = (size_t)l*TW_LAYER;
        k_wsplit<<<(256*192 + 255)/256, 256>>>(W_off + (size_t)l*D*192, p_twh + lb + TW_OFF, p_twl + lb + TW_OFF, 256, 192);
        k_wsplit<<<(256*96  + 255)/256, 256>>>(W_att + (size_t)l*D*96,  p_twh + lb + TW_ATT, p_twl + lb + TW_ATT, 256, 96);
        k_wsplit<<<(256*256 + 255)/256, 256>>>(W_out + (size_t)l*D*D,   p_twh + lb + TW_OUT, p_twl + lb + TW_OUT, 256, 256);
        k_wsplit<<<(256*512 + 255)/256, 256>>>(W_ff1 + (size_t)l*D*FFN, p_twh + lb + TW_FF1, p_twl + lb + TW_FF1, 256, 512);
        k_wsplit<<<(512*256 + 255)/256, 256>>>(W_ff2 + (size_t)l*FFN*D, p_twh + lb + TW_FF2, p_twl + lb + TW_FF2, 512, 256);
    }

    // stage A: restore + cam_x output
    k_restore<<<CAMS*L, 256>>>(camera_x, ids, mask_tok, p_full, out + XOUT_SZ);

    // stage B: feature projection (fp32; W_tc is (N,K) -> TB)
    gemm_k<4, true><<<dim3(4, 17), 256>>>(p_full, W_tc, p_feat, CAMS*L, D, IN_C,
                                          b_tc, cams_emb, lvl_emb);

    cudaMemcpyAsync(p_q, vol_emb, (size_t)NQ*D*sizeof(float), cudaMemcpyDeviceToDevice);

    const int MBT = (NQ + 127) / 128;   // 157
    for (int l = 0; l < LAYERS; l++) {
        size_t lb = (size_t)l*TW_LAYER;
        gemm_k<1, false><<<dim3(4, 17), 256>>>(p_feat, W_val + (size_t)l*D*D, p_val,
                                               CAMS*L, D, D, b_val + l*D, nullptr, nullptr);
        tgemm<1><<<dim3(3, MBT), 256>>>(p_q, p_twh + lb + TW_OFF, p_twl + lb + TW_OFF,
                                        p_off, NQ, 192, 256, b_off + l*192, nullptr, 0,0,0);
        tgemm<1><<<dim3(2, MBT), 256>>>(p_q, p_twh + lb + TW_ATT, p_twl + lb + TW_ATT,
                                        p_att, NQ, 96, 256, b_att + l*96, nullptr, 0,0,0);
        k_softmax12<<<(NQ*HEADS + 255)/256, 256>>>(p_att);
        k_sample<<<NQ, 256>>>(p_off, p_att, p_val, p_agg);
        tgemm<3><<<dim3(4, MBT), 256>>>(p_agg, p_twh + lb + TW_OUT, p_twl + lb + TW_OUT,
                                        p_qt, NQ, 256, 256, b_out + l*D, p_q, 0,0,0);
        k_ln<<<NQ, 256>>>(p_qt, p_q, ln1_g + l*D, ln1_b + l*D);
        tgemm<2><<<dim3(8, MBT), 256>>>(p_q, p_twh + lb + TW_FF1, p_twl + lb + TW_FF1,
                                        p_h1, NQ, 512, 256, b_ff1 + l*FFN, nullptr, 0,0,0);
        tgemm<3><<<dim3(4, MBT), 256>>>(p_h1, p_twh + lb + TW_FF2, p_twl + lb + TW_FF2,
                                        p_qt, NQ, 256, 512, b_ff2 + l*D, p_q, 0,0,0);
        k_ln<<<NQ, 256>>>(p_qt, p_q, ln2_g + l*D, ln2_b + l*D);
    }

    // deconv as 8 parity tensor GEMMs (scatter epilogue)
    for (int r = 0; r < 8; r++) {
        tgemm<5><<<dim3(4, MBT), 256>>>(p_q, p_dwh + (size_t)r*D*D, p_dwl + (size_t)r*D*D,
                                        p_x1, NQ, 256, 256, nullptr, nullptr,
                                        (r >> 2) & 1, (r >> 1) & 1, r & 1);
    }

    // group norm 1 stats (apply is fused into prep)
    {
        long glen = 16L * (long)SPAT;
        k_gn_zero<<<1, 32>>>(p_sum);
        k_gn_stats<<<dim3(16, 64), 256>>>(p_x1, p_sum, glen);
        k_gn_fin<<<1, 32>>>(p_sum, p_mi, glen);
    }

    // fused GN1 apply + relu + transpose + fp16 split into padded planes
    k_prep_gn<<<dim3(2500, 4), 256>>>(p_x1, p_mi, gn1_g, gn1_b, p_xh, p_xl);

    // conv3 via fp16 2-term mma.sync
    k_conv3_v4<<<dim3(SX/2, SY/4), 512, CV_SMEM>>>(p_xh, p_xl, p_wh, out);

    // group norm 2 + relu
    {
        long glen = 12L * (long)SPAT;
        k_gn_zero<<<1, 32>>>(p_sum);
        k_gn_stats<<<dim3(16, 64), 256>>>(out, p_sum, glen);
        k_gn_fin<<<1, 32>>>(p_sum, p_mi, glen);
        k_gn_apply<<<4096, 256>>>(out, p_mi, gn2_g, gn2_b, 12, (long)SPAT, (long)OC3*SPAT);
    }
}

// round 8
// speedup vs baseline: 3.9676x; 1.2137x over previous
#include <cuda_runtime.h>
#include <cuda_bf16.h>
#include <cuda_fp16.h>
#include <cstddef>
#include <cstdint>

typedef unsigned short u16;

// ---------------- problem constants ----------------
#define CAMS 6
#define HEADS 8
#define PTS 2
#define LAYERS 3
#define D 256
#define DH 32
#define FFN 512
#define VZ 8
#define VH 50
#define VW 50
#define NQ (VZ*VH*VW)          // 20000
#define IN_C 768
#define FH 8
#define FW 22
#define L 176
#define LVIS 44

#define X1_C 256
#define SX 100
#define SY 100
#define SZ 16
#define SPAT ((size_t)SX*SY*SZ)   // 160000
#define OC3 192

#define XOUT_SZ ((size_t)OC3*SPAT)

// padded split-input planes for conv3 (ic-fastest)
#define XP 102
#define YP 102
#define ZP 18

// transformer split-weight layout offsets (per layer, [N][K] hi/lo)
#define TW_OFF   0
#define TW_ATT   49152
#define TW_OUT   73728
#define TW_FF1   139264
#define TW_FF2   270336
#define TW_LAYER 401408

// ---------------- scratch ----------------
__device__ float g_full[CAMS*L*IN_C];
__device__ float g_feat[CAMS*L*D];
__device__ float g_val [CAMS*L*D];
__device__ float g_off [NQ*HEADS*CAMS*PTS*2];
__device__ float g_att [NQ*HEADS*CAMS*PTS];
__device__ float g_agg [NQ*D];
__device__ float g_q   [NQ*D];
__device__ float g_qt  [NQ*D];
__device__ float g_h1  [NQ*FFN];
__device__ float g_x1  [(size_t)X1_C*SX*SY*SZ];
__device__ u16 g_xh[(size_t)XP*YP*ZP*256];      // fp16 plane (single term)
__device__ u16 g_wh[27*OC3*256];                // fp16 conv weights [tap][oc][ic]
__device__ u16 g_twh[3*TW_LAYER];
__device__ u16 g_twl[3*TW_LAYER];
__device__ u16 g_dwh[8*D*D];
__device__ u16 g_dwl[8*D*D];
__device__ double g_gnsum[32];
__device__ float  g_gnmi[32];

// ---------------- helpers ----------------
__device__ __forceinline__ uint32_t smem_u32(const void* p)
{
    uint32_t a;
    asm("{ .reg .u64 t; cvta.to.shared.u64 t, %1; cvt.u32.u64 %0, t; }" : "=r"(a) : "l"(p));
    return a;
}

__device__ __forceinline__ void split_bf16(float v, u16& h, u16& l)
{
    __nv_bfloat16 bh = __float2bfloat16(v);
    float fh = __bfloat162float(bh);
    __nv_bfloat16 bl = __float2bfloat16(v - fh);
    h = __bfloat16_as_ushort(bh);
    l = __bfloat16_as_ushort(bl);
}

__device__ __forceinline__ void mma_bf16(float* c, const unsigned* a, const unsigned* b)
{
    asm volatile(
        "mma.sync.aligned.m16n8k16.row.col.f32.bf16.bf16.f32 "
        "{%0,%1,%2,%3}, {%4,%5,%6,%7}, {%8,%9}, {%0,%1,%2,%3};\n"
        : "+f"(c[0]), "+f"(c[1]), "+f"(c[2]), "+f"(c[3])
        : "r"(a[0]), "r"(a[1]), "r"(a[2]), "r"(a[3]), "r"(b[0]), "r"(b[1]));
}

__device__ __forceinline__ void mma_fp16(float* c, const unsigned* a, const unsigned* b)
{
    asm volatile(
        "mma.sync.aligned.m16n8k16.row.col.f32.f16.f16.f32 "
        "{%0,%1,%2,%3}, {%4,%5,%6,%7}, {%8,%9}, {%0,%1,%2,%3};\n"
        : "+f"(c[0]), "+f"(c[1]), "+f"(c[2]), "+f"(c[3])
        : "r"(a[0]), "r"(a[1]), "r"(a[2]), "r"(a[3]), "r"(b[0]), "r"(b[1]));
}

#define CP_ASYNC16(dst, src) \
    asm volatile("cp.async.cg.shared.global [%0], [%1], 16;\n" :: "r"(dst), "l"(src))
#define CP_COMMIT() asm volatile("cp.async.commit_group;\n")
#define CP_WAIT1() asm volatile("cp.async.wait_group 1;\n")
#define CP_WAIT0() asm volatile("cp.async.wait_group 0;\n")

// ---------------- restore tokens + write cam_x output ----------------
__global__ void k_restore(const float* __restrict__ camx,
                          const int* __restrict__ ids,
                          const float* __restrict__ mask_tok,
                          float* __restrict__ full,
                          float* __restrict__ camx_out)
{
    int tok = blockIdx.x;
    int n = tok / L, p = tok % L;
    int t = ids[n*L + p];
    for (int c = threadIdx.x; c < IN_C; c += blockDim.x) {
        float v = (t < LVIS) ? camx[((size_t)n*LVIS + t)*IN_C + c] : mask_tok[c];
        full[(size_t)tok*IN_C + c] = v;
        camx_out[((size_t)n*IN_C + c)*L + p] = v;
    }
}

// ---------------- fp32 tiled SGEMM (small matrices only) ----------------
// MODE: 1 +bias, 4 feat
#define TM 64
#define TN 64
#define TKK 16
template<int MODE, bool TB>
__global__ void gemm_k(const float* __restrict__ A, const float* __restrict__ B,
                       float* __restrict__ C, int M, int N, int K,
                       const float* __restrict__ bias,
                       const float* __restrict__ e1, const float* __restrict__ e2)
{
    __shared__ float As[TKK][TM+4];
    __shared__ float Bs[TKK][TN+4];
    int m0 = blockIdx.y * TM, n0 = blockIdx.x * TN;
    int t = threadIdx.x;
    int tx = t & 15, ty = t >> 4;
    float acc[4][4] = {};
    for (int k0 = 0; k0 < K; k0 += TKK) {
        for (int i = t; i < TM*TKK; i += 256) {
            int mm = i >> 4, kk = i & 15;
            int m = m0 + mm, k = k0 + kk;
            As[kk][mm] = (m < M && k < K) ? A[(size_t)m*K + k] : 0.f;
        }
        if (!TB) {
            for (int i = t; i < TKK*TN; i += 256) {
                int kk = i >> 6, nn = i & 63;
                int k = k0 + kk, n = n0 + nn;
                Bs[kk][nn] = (k < K && n < N) ? B[(size_t)k*N + n] : 0.f;
            }
        } else {
            for (int i = t; i < TKK*TN; i += 256) {
                int nn = i >> 4, kk = i & 15;
                int k = k0 + kk, n = n0 + nn;
                Bs[kk][nn] = (k < K && n < N) ? B[(size_t)n*K + k] : 0.f;
            }
        }
        __syncthreads();
        #pragma unroll
        for (int kk = 0; kk < TKK; kk++) {
            float a[4], b[4];
            #pragma unroll
            for (int i = 0; i < 4; i++) a[i] = As[kk][ty*4 + i];
            #pragma unroll
            for (int j = 0; j < 4; j++) b[j] = Bs[kk][tx*4 + j];
            #pragma unroll
            for (int i = 0; i < 4; i++)
                #pragma unroll
                for (int j = 0; j < 4; j++) acc[i][j] += a[i]*b[j];
        }
        __syncthreads();
    }
    #pragma unroll
    for (int i = 0; i < 4; i++) {
        int row = m0 + ty*4 + i;
        if (row >= M) continue;
        #pragma unroll
        for (int j = 0; j < 4; j++) {
            int col = n0 + tx*4 + j;
            if (col >= N) continue;
            float v = acc[i][j];
            if (MODE == 1) v += bias[col];
            else if (MODE == 4) {
                v += bias[col]; v = v > 0.f ? v : 0.f;
                v += e1[(row/L)*D + col] + e2[col];
            }
            C[(size_t)row*N + col] = v;
        }
    }
}

// ---------------- tensor GEMM: C = A(fp32 MxK) @ Bsplit([N][K] bf16 hi/lo) ----------------
// 3-term bf16 split. Tile 128M x 64N, 256 threads.
// MODE: 1 +bias, 2 relu(+bias), 3 +bias+res, 5 deconv scatter
template<int MODE>
__global__ void __launch_bounds__(256) tgemm(const float* __restrict__ A,
                                             const u16* __restrict__ Bh,
                                             const u16* __restrict__ Bl,
                                             float* __restrict__ C, int M, int N, int K,
                                             const float* __restrict__ bias,
                                             const float* __restrict__ res,
                                             int p1, int p2, int p3)
{
    __shared__ u16 Ah[128*40], Al[128*40], Bsh[64*40], Bsl[64*40];
    int m0 = blockIdx.y * 128, n0 = blockIdx.x * 64;
    int tid = threadIdx.x, lane = tid & 31, wrp = tid >> 5;
    int wm = wrp & 3, wn = wrp >> 2;
    int q = lane & 3, rr = lane >> 2;

    float acc[2][4][4] = {};
    const unsigned* pah = (const unsigned*)Ah;
    const unsigned* pal = (const unsigned*)Al;
    const unsigned* pbh = (const unsigned*)Bsh;
    const unsigned* pbl = (const unsigned*)Bsl;

    for (int k0 = 0; k0 < K; k0 += 32) {
        __syncthreads();
        #pragma unroll
        for (int it = 0; it < 16; it++) {
            int i = tid + it*256;
            int row = i >> 5, k = i & 31;
            int m = m0 + row;
            float v = (m < M) ? A[(size_t)m*K + k0 + k] : 0.f;
            u16 h, l; split_bf16(v, h, l);
            Ah[row*40 + k] = h;
            Al[row*40 + k] = l;
        }
        #pragma unroll
        for (int it = 0; it < 4; it++) {
            int i = tid + it*256;
            int pl = i >> 9; int idx = i & 511;
            int n = idx >> 3, seg = idx & 7;
            uint2 v = make_uint2(0u, 0u);
            if (n0 + n < N) {
                const u16* src = (pl ? Bl : Bh) + (size_t)(n0 + n)*K + k0 + seg*4;
                v = *(const uint2*)src;
            }
            *(uint2*)((pl ? Bsl : Bsh) + n*40 + seg*4) = v;
        }
        __syncthreads();
        #pragma unroll
        for (int ks = 0; ks < 2; ks++) {
            int o = ks*8 + q;
            unsigned ah[2][4], al[2][4], bh[4][2], bl[4][2];
            #pragma unroll
            for (int mi = 0; mi < 2; mi++) {
                int ra = wm*32 + mi*16 + rr, rb = ra + 8;
                ah[mi][0] = pah[ra*20 + o]; ah[mi][1] = pah[rb*20 + o];
                ah[mi][2] = pah[ra*20 + o + 4]; ah[mi][3] = pah[rb*20 + o + 4];
                al[mi][0] = pal[ra*20 + o]; al[mi][1] = pal[rb*20 + o];
                al[mi][2] = pal[ra*20 + o + 4]; al[mi][3] = pal[rb*20 + o + 4];
            }
            #pragma unroll
            for (int nj = 0; nj < 4; nj++) {
                int n = wn*32 + nj*8 + rr;
                bh[nj][0] = pbh[n*20 + o]; bh[nj][1] = pbh[n*20 + o + 4];
                bl[nj][0] = pbl[n*20 + o]; bl[nj][1] = pbl[n*20 + o + 4];
            }
            #pragma unroll
            for (int mi = 0; mi < 2; mi++)
                #pragma unroll
                for (int nj = 0; nj < 4; nj++) {
                    mma_bf16(acc[mi][nj], ah[mi], bh[nj]);
                    mma_bf16(acc[mi][nj], ah[mi], bl[nj]);
                    mma_bf16(acc[mi][nj], al[mi], bh[nj]);
                }
        }
    }

    #pragma unroll
    for (int mi = 0; mi < 2; mi++) {
        int r0 = m0 + wm*32 + mi*16 + rr;
        #pragma unroll
        for (int nj = 0; nj < 4; nj++) {
            int col = n0 + wn*32 + nj*8 + 2*q;
            #pragma unroll
            for (int hh = 0; hh < 2; hh++) {
                int row = r0 + hh*8;
                if (row >= M) continue;
                #pragma unroll
                for (int cc = 0; cc < 2; cc++) {
                    int c = col + cc;
                    if (c >= N) continue;
                    float v = acc[mi][nj][hh*2 + cc];
                    if (MODE == 1) v += bias[c];
                    else if (MODE == 2) { v += bias[c]; v = v > 0.f ? v : 0.f; }
                    else if (MODE == 3) v += bias[c] + res[(size_t)row*N + c];
                    if (MODE == 5) {
                        int x = row % VW, y = (row / VW) % VH, z = row / (VW*VH);
                        size_t idx = (((size_t)c*SX + (2*x+p1))*SY + (2*y+p2))*SZ + (2*z+p3);
                        C[idx] = v;
                    } else {
                        C[(size_t)row*N + c] = v;
                    }
                }
            }
        }
    }
}

// ---------------- weight split: W [K][N] fp32 -> bh/bl [N][K] (bf16) ----------------
__global__ void k_wsplit(const float* __restrict__ W, u16* __restrict__ bh,
                         u16* __restrict__ bl, int K, int N)
{
    int i = blockIdx.x * blockDim.x + threadIdx.x;
    if (i >= K*N) return;
    int n = i / K, k = i % K;
    u16 h, l; split_bf16(W[(size_t)k*N + n], h, l);
    bh[i] = h; bl[i] = l;
}

// deconv weights: per parity r, [N=oc][K=ic] bf16 split
__global__ void k_wdt2(const float* __restrict__ w, u16* __restrict__ dh, u16* __restrict__ dl)
{
    int i = blockIdx.x * blockDim.x + threadIdx.x;
    if (i >= 8*D*D) return;
    int ic = i & 255, o = (i >> 8) & 255, r = i >> 16;
    int r1 = (r >> 2) & 1, r2 = (r >> 1) & 1, r3 = r & 1;
    float v = w[((size_t)o*D + ic)*8 + ((1-r1)*4 + (1-r2)*2 + (1-r3))];
    u16 h, l; split_bf16(v, h, l);
    size_t idx = ((size_t)r*D + o)*D + ic;
    dh[idx] = h; dl[idx] = l;
}

// ---------------- softmax over 12 per (query, head) ----------------
__global__ void k_softmax12(float* __restrict__ att)
{
    int i = blockIdx.x * blockDim.x + threadIdx.x;
    if (i >= NQ*HEADS) return;
    float* p = att + (size_t)(i/HEADS)*(HEADS*12) + (i%HEADS)*12;
    float mx = -1e30f;
    #pragma unroll
    for (int k = 0; k < 12; k++) mx = fmaxf(mx, p[k]);
    float s = 0.f;
    float e[12];
    #pragma unroll
    for (int k = 0; k < 12; k++) { e[k] = __expf(p[k]-mx); s += e[k]; }
    float inv = 1.f/s;
    #pragma unroll
    for (int k = 0; k < 12; k++) p[k] = e[k]*inv;
}

// ---------------- bilinear sampling + aggregation ----------------
__global__ void k_sample(const float* __restrict__ off, const float* __restrict__ att,
                         const float* __restrict__ val, float* __restrict__ agg)
{
    int n = blockIdx.x;
    int t = threadIdx.x;
    __shared__ float off_s[HEADS*CAMS*PTS*2];
    __shared__ float att_s[HEADS*CAMS*PTS];
    if (t < 192) off_s[t] = off[(size_t)n*192 + t];
    if (t < 96)  att_s[t] = att[(size_t)n*96 + t];
    __syncthreads();
    int h = t >> 5, dh = t & 31;
    int qx = n % VW, qy = (n / VW) % VH;
    float refx = (qx + 0.5f) * ((float)FW / VW) - 0.5f;
    float refy = (qy + 0.5f) * ((float)FH / VH) - 0.5f;
    float acc = 0.f;
    #pragma unroll
    for (int c = 0; c < CAMS; c++) {
        #pragma unroll
        for (int p = 0; p < PTS; p++) {
            int base = ((h*CAMS + c)*PTS + p)*2;
            float x = refx + off_s[base];
            float y = refy + off_s[base+1];
            float x0f = floorf(x), y0f = floorf(y);
            float wx = x - x0f, wy = y - y0f;
            int x0 = (int)x0f, y0 = (int)y0f;
            int xc0 = min(max(x0, 0), FW-1),   xc1 = min(max(x0+1, 0), FW-1);
            int yc0 = min(max(y0, 0), FH-1),   yc1 = min(max(y0+1, 0), FH-1);
            const float* vb = val + ((size_t)c*L*HEADS + h)*DH + dh;
            float v00 = vb[(size_t)(yc0*FW + xc0)*HEADS*DH];
            float v01 = vb[(size_t)(yc0*FW + xc1)*HEADS*DH];
            float v10 = vb[(size_t)(yc1*FW + xc0)*HEADS*DH];
            float v11 = vb[(size_t)(yc1*FW + xc1)*HEADS*DH];
            float bil = (1.f-wx)*(1.f-wy)*v00 + wx*(1.f-wy)*v01
                      + (1.f-wx)*wy*v10 + wx*wy*v11;
            acc += att_s[h*12 + c*2 + p] * bil;
        }
    }
    agg[(size_t)n*D + h*DH + dh] = acc;
}

// ---------------- layernorm (row of 256) ----------------
__global__ void k_ln(const float* __restrict__ in, float* __restrict__ out,
                     const float* __restrict__ g, const float* __restrict__ b)
{
    int n = blockIdx.x, t = threadIdx.x;
    float x = in[(size_t)n*D + t];
    float s = x, s2 = x*x;
    #pragma unroll
    for (int o = 16; o; o >>= 1) {
        s  += __shfl_xor_sync(0xffffffffu, s,  o);
        s2 += __shfl_xor_sync(0xffffffffu, s2, o);
    }
    __shared__ float ws[8], ws2[8], mv[2];
    if ((t & 31) == 0) { ws[t>>5] = s; ws2[t>>5] = s2; }
    __syncthreads();
    if (t < 32) {
        float a = (t < 8) ? ws[t] : 0.f, a2 = (t < 8) ? ws2[t] : 0.f;
        #pragma unroll
        for (int o = 4; o; o >>= 1) {
            a  += __shfl_xor_sync(0xffffffffu, a,  o);
            a2 += __shfl_xor_sync(0xffffffffu, a2, o);
        }
        if (t == 0) {
            float m = a / D;
            float v = a2 / D - m*m;
            mv[0] = m; mv[1] = rsqrtf(v + 1e-5f);
        }
    }
    __syncthreads();
    out[(size_t)n*D + t] = (x - mv[0]) * mv[1] * g[t] + b[t];
}

// ---------------- group norm ----------------
__global__ void k_gn_zero(double* sums) { if (threadIdx.x < 32) sums[threadIdx.x] = 0.0; }

__global__ void k_gn_stats(const float* __restrict__ x, double* __restrict__ sums, long glen)
{
    int g = blockIdx.x;
    const float* p = x + (size_t)g * glen;
    double s = 0.0, s2 = 0.0;
    for (long i = (long)blockIdx.y*blockDim.x + threadIdx.x; i < glen;
         i += (long)gridDim.y*blockDim.x) {
        float v = p[i];
        s += v; s2 += (double)v*v;
    }
    __shared__ double sh[256], sh2[256];
    sh[threadIdx.x] = s; sh2[threadIdx.x] = s2;
    __syncthreads();
    for (int o = 128; o; o >>= 1) {
        if (threadIdx.x < o) { sh[threadIdx.x] += sh[threadIdx.x+o]; sh2[threadIdx.x] += sh2[threadIdx.x+o]; }
        __syncthreads();
    }
    if (threadIdx.x == 0) {
        atomicAdd(&sums[g*2],   sh[0]);
        atomicAdd(&sums[g*2+1], sh2[0]);
    }
}

__global__ void k_gn_fin(const double* __restrict__ sums, float* __restrict__ mi, long glen)
{
    int g = threadIdx.x;
    if (g < 16) {
        double m = sums[g*2] / (double)glen;
        double v = sums[g*2+1] / (double)glen - m*m;
        mi[g*2]   = (float)m;
        mi[g*2+1] = (float)(1.0 / sqrt(v + 1e-5));
    }
}

__global__ void k_gn_apply(float* __restrict__ x, const float* __restrict__ mi,
                           const float* __restrict__ gg, const float* __restrict__ gb,
                           int cpg, long S, long total)
{
    for (long i = (long)blockIdx.x*blockDim.x + threadIdx.x; i < total;
         i += (long)gridDim.x*blockDim.x) {
        int c = (int)(i / S);
        int grp = c / cpg;
        float v = (x[i] - mi[grp*2]) * mi[grp*2+1] * gg[c] + gb[c];
        x[i] = v > 0.f ? v : 0.f;
    }
}

// ---------------- fused GN1 apply + transpose + fp16 convert into padded plane ----------------
__global__ void k_prep_gn(const float* __restrict__ x1, const float* __restrict__ mi,
                          const float* __restrict__ gg, const float* __restrict__ gb,
                          u16* __restrict__ xh)
{
    __shared__ float ts[64][65];
    int s0 = blockIdx.x * 64;
    int ic0 = blockIdx.y * 64;
    int tid = threadIdx.x;
    int col = tid & 63, r4 = tid >> 6;
    #pragma unroll
    for (int j = 0; j < 16; j++) {
        int ic = r4 + j*4;
        ts[ic][col] = x1[(size_t)(ic0+ic)*SPAT + s0 + col];
    }
    __syncthreads();
    int c = ic0 + col;
    int grp = c >> 4;                // GN1: 16 channels per group
    float m = mi[grp*2], inv = mi[grp*2+1];
    float gc = gg[c], bc = gb[c];
    #pragma unroll
    for (int j = 0; j < 16; j++) {
        int sp = r4 + j*4;
        int s = s0 + sp;
        int z = s & 15; int t2 = s >> 4; int y = t2 % SY; int x = t2 / SY;
        size_t base = ((size_t)((x+1)*YP + (y+1))*ZP + (z+1))*256 + ic0;
        float v = (ts[col][sp] - m) * inv * gc + bc;
        v = v > 0.f ? v : 0.f;
        xh[base + col] = __half_as_ushort(__float2half_rn(v));
    }
}

__global__ void k_wprep2(const float* __restrict__ w, u16* __restrict__ wh)
{
    int i = blockIdx.x * blockDim.x + threadIdx.x;
    if (i >= 27*OC3*256) return;
    int ic = i & 255; int t = i >> 8;
    int oc = t % OC3; int tap = t / OC3;
    wh[((size_t)tap*OC3 + oc)*256 + ic] =
        __half_as_ushort(__float2half_rn(w[((size_t)oc*X1_C + ic)*27 + tap]));
}

// ---------------- conv3 v5: single fp16, cp.async double-buffered weights ----------------
// Block: 2x x 4y x 16z (M=128) x 192 oc. ic chunk 32. 512 threads, 16 warps 4m x 4n.
#define CV_AHI 0
#define CV_W   34560
#define CV_WBUF 15360
#define CV_SMEM 65280

__global__ void __launch_bounds__(512) k_conv3_v5(const u16* __restrict__ xh,
                                                  const u16* __restrict__ wh,
                                                  float* __restrict__ out)
{
    extern __shared__ unsigned char sm[];
    uint32_t smb = smem_u32(sm);
    int tid = threadIdx.x, lane = tid & 31, wrp = tid >> 5;
    int wm = wrp & 3, wn = wrp >> 2;
    int q = lane & 3, rr = lane >> 2;
    int xo = wm >> 1, yb = (wm & 1) * 2;
    int x0 = blockIdx.x * 2, y0 = blockIdx.y * 4;

    float acc[2][6][4];
    #pragma unroll
    for (int f = 0; f < 2; f++)
        #pragma unroll
        for (int j = 0; j < 6; j++)
            #pragma unroll
            for (int k = 0; k < 4; k++) acc[f][j][k] = 0.f;

    const unsigned* pah = (const unsigned*)(sm + CV_AHI);

    for (int c = 0; c < 8; c++) {
        int ic0 = c * 32;
        // issue A chunk (432 rows x 32 ic) -> 1728 cp.async
        #pragma unroll
        for (int it = 0; it < 4; it++) {
            int i = tid + it*512;
            if (i < 1728) {
                int row = i >> 2, seg = i & 3;
                int zz = row % 18; int t1 = row / 18;
                int yy = t1 % 6, xx = t1 / 6;
                const u16* src = xh
                    + ((size_t)((x0+xx)*YP + (y0+yy))*ZP + zz)*256 + ic0 + seg*8;
                uint32_t dst = smb + CV_AHI + row*80 + seg*16;
                CP_ASYNC16(dst, src);
            }
        }
        // issue W tap0 -> buf0 (192 rows x 32 ic) -> 768 cp.async
        #pragma unroll
        for (int it = 0; it < 2; it++) {
            int i = tid + it*512;
            if (i < 768) {
                int row = i >> 2, seg = i & 3;
                const u16* src = wh + ((size_t)(0*OC3 + row))*256 + ic0 + seg*8;
                uint32_t dst = smb + CV_W + row*80 + seg*16;
                CP_ASYNC16(dst, src);
            }
        }
        CP_COMMIT();

        for (int tap = 0; tap < 27; tap++) {
            int cur = tap & 1;
            if (tap < 26) {
                int nb = (tap + 1) & 1;
                #pragma unroll
                for (int it = 0; it < 2; it++) {
                    int i = tid + it*512;
                    if (i < 768) {
                        int row = i >> 2, seg = i & 3;
                        const u16* src = wh + ((size_t)((tap+1)*OC3 + row))*256 + ic0 + seg*8;
                        uint32_t dst = smb + CV_W + nb*CV_WBUF + row*80 + seg*16;
                        CP_ASYNC16(dst, src);
                    }
                }
                CP_COMMIT();
                CP_WAIT1();
            } else {
                CP_WAIT0();
            }
            __syncthreads();

            int k1 = tap / 9, k2 = (tap / 3) % 3, k3 = tap % 3;
            const unsigned* pw = (const unsigned*)(sm + CV_W + cur*CV_WBUF);

            #pragma unroll
            for (int ks = 0; ks < 2; ks++) {
                int o = ks*8 + q;
                unsigned ah[2][4], b[6][2];
                #pragma unroll
                for (int f = 0; f < 2; f++) {
                    int ra = ((xo + k1)*6 + (yb + f + k2))*18 + rr + k3;
                    int rb = ra + 8;
                    ah[f][0] = pah[ra*20 + o]; ah[f][1] = pah[rb*20 + o];
                    ah[f][2] = pah[ra*20 + o + 4]; ah[f][3] = pah[rb*20 + o + 4];
                }
                #pragma unroll
                for (int j = 0; j < 6; j++) {
                    int n = wn*48 + j*8 + rr;
                    b[j][0] = pw[n*20 + o]; b[j][1] = pw[n*20 + o + 4];
                }
                #pragma unroll
                for (int f = 0; f < 2; f++)
                    #pragma unroll
                    for (int j = 0; j < 6; j++)
                        mma_fp16(acc[f][j], ah[f], b[j]);
            }
            __syncthreads();
        }
    }

    #pragma unroll
    for (int f = 0; f < 2; f++) {
        int Xg = x0 + xo, Yg = y0 + yb + f;
        #pragma unroll
        for (int j = 0; j < 6; j++) {
            int oc = wn*48 + j*8 + 2*q;
            size_t base = (((size_t)oc*SX + Xg)*SY + Yg)*SZ;
            out[base + rr]            = acc[f][j][0];
            out[base + rr + 8]        = acc[f][j][2];
            out[base + SPAT + rr]     = acc[f][j][1];
            out[base + SPAT + rr + 8] = acc[f][j][3];
        }
    }
}

// ---------------- host orchestration ----------------
extern "C" void kernel_launch(void* const* d_in, const int* in_sizes, int n_in,
                              void* d_out, int out_size)
{
    int shift = 0;
    if (n_in >= 4 && in_sizes[2] == 1 && in_sizes[3] == 1) shift = 0;
    else shift = 2;
    #define IN(i) ((i) >= 2 ? d_in[(i) - shift] : d_in[(i)])

    const float* camera_x  = (const float*)IN(0);
    const int*   ids       = (const int*)  IN(1);
    const float* mask_tok  = (const float*)IN(4);
    const float* vol_emb   = (const float*)IN(5);
    const float* W_tc      = (const float*)IN(6);
    const float* b_tc      = (const float*)IN(7);
    const float* cams_emb  = (const float*)IN(8);
    const float* lvl_emb   = (const float*)IN(9);
    const float* W_off     = (const float*)IN(10);
    const float* b_off     = (const float*)IN(11);
    const float* W_att     = (const float*)IN(12);
    const float* b_att     = (const float*)IN(13);
    const float* W_val     = (const float*)IN(14);
    const float* b_val     = (const float*)IN(15);
    const float* W_out     = (const float*)IN(16);
    const float* b_out     = (const float*)IN(17);
    const float* ln1_g     = (const float*)IN(18);
    const float* ln1_b     = (const float*)IN(19);
    const float* W_ff1     = (const float*)IN(20);
    const float* b_ff1     = (const float*)IN(21);
    const float* W_ff2     = (const float*)IN(22);
    const float* b_ff2     = (const float*)IN(23);
    const float* ln2_g     = (const float*)IN(24);
    const float* ln2_b     = (const float*)IN(25);
    const float* deconv_w  = (const float*)IN(26);
    const float* gn1_g     = (const float*)IN(27);
    const float* gn1_b     = (const float*)IN(28);
    const float* conv3_w   = (const float*)IN(29);
    const float* gn2_g     = (const float*)IN(30);
    const float* gn2_b     = (const float*)IN(31);
    #undef IN

    float* out = (float*)d_out;

    static int cfg = 0;
    if (!cfg) {
        cudaFuncSetAttribute(k_conv3_v5, cudaFuncAttributeMaxDynamicSharedMemorySize, CV_SMEM);
        cfg = 1;
    }

    float *p_full, *p_feat, *p_val, *p_off, *p_att, *p_agg, *p_q, *p_qt, *p_h1, *p_x1, *p_mi;
    u16 *p_xh, *p_wh, *p_twh, *p_twl, *p_dwh, *p_dwl;
    double* p_sum;
    cudaGetSymbolAddress((void**)&p_full, g_full);
    cudaGetSymbolAddress((void**)&p_feat, g_feat);
    cudaGetSymbolAddress((void**)&p_val,  g_val);
    cudaGetSymbolAddress((void**)&p_off,  g_off);
    cudaGetSymbolAddress((void**)&p_att,  g_att);
    cudaGetSymbolAddress((void**)&p_agg,  g_agg);
    cudaGetSymbolAddress((void**)&p_q,    g_q);
    cudaGetSymbolAddress((void**)&p_qt,   g_qt);
    cudaGetSymbolAddress((void**)&p_h1,   g_h1);
    cudaGetSymbolAddress((void**)&p_x1,   g_x1);
    cudaGetSymbolAddress((void**)&p_xh,   g_xh);
    cudaGetSymbolAddress((void**)&p_wh,   g_wh);
    cudaGetSymbolAddress((void**)&p_twh,  g_twh);
    cudaGetSymbolAddress((void**)&p_twl,  g_twl);
    cudaGetSymbolAddress((void**)&p_dwh,  g_dwh);
    cudaGetSymbolAddress((void**)&p_dwl,  g_dwl);
    cudaGetSymbolAddress((void**)&p_sum,  g_gnsum);
    cudaGetSymbolAddress((void**)&p_mi,   g_gnmi);

    // halo zeroing for conv plane
    cudaMemsetAsync(p_xh, 0, (size_t)XP*YP*ZP*256*sizeof(u16));

    // weight preprocessing (independent)
    k_wprep2<<<(27*OC3*256 + 255)/256, 256>>>(conv3_w, p_wh);
    k_wdt2<<<(8*D*D + 255)/256, 256>>>(deconv_w, p_dwh, p_dwl);
    for (int l = 0; l < LAYERS; l++) {
        size_t lb = (size_t)l*TW_LAYER;
        k_wsplit<<<(256*192 + 255)/256, 256>>>(W_off + (size_t)l*D*192, p_twh + lb + TW_OFF, p_twl + lb + TW_OFF, 256, 192);
        k_wsplit<<<(256*96  + 255)/256, 256>>>(W_att + (size_t)l*D*96,  p_twh + lb + TW_ATT, p_twl + lb + TW_ATT, 256, 96);
        k_wsplit<<<(256*256 + 255)/256, 256>>>(W_out + (size_t)l*D*D,   p_twh + lb + TW_OUT, p_twl + lb + TW_OUT, 256, 256);
        k_wsplit<<<(256*512 + 255)/256, 256>>>(W_ff1 + (size_t)l*D*FFN, p_twh + lb + TW_FF1, p_twl + lb + TW_FF1, 256, 512);
        k_wsplit<<<(512*256 + 255)/256, 256>>>(W_ff2 + (size_t)l*FFN*D, p_twh + lb + TW_FF2, p_twl + lb + TW_FF2, 512, 256);
    }

    // stage A: restore + cam_x output
    k_restore<<<CAMS*L, 256>>>(camera_x, ids, mask_tok, p_full, out + XOUT_SZ);

    // stage B: feature projection (fp32; W_tc is (N,K) -> TB)
    gemm_k<4, true><<<dim3(4, 17), 256>>>(p_full, W_tc, p_feat, CAMS*L, D, IN_C,
                                          b_tc, cams_emb, lvl_emb);

    cudaMemcpyAsync(p_q, vol_emb, (size_t)NQ*D*sizeof(float), cudaMemcpyDeviceToDevice);

    const int MBT = (NQ + 127) / 128;   // 157
    for (int l = 0; l < LAYERS; l++) {
        size_t lb = (size_t)l*TW_LAYER;
        gemm_k<1, false><<<dim3(4, 17), 256>>>(p_feat, W_val + (size_t)l*D*D, p_val,
                                               CAMS*L, D, D, b_val + l*D, nullptr, nullptr);
        tgemm<1><<<dim3(3, MBT), 256>>>(p_q, p_twh + lb + TW_OFF, p_twl + lb + TW_OFF,
                                        p_off, NQ, 192, 256, b_off + l*192, nullptr, 0,0,0);
        tgemm<1><<<dim3(2, MBT), 256>>>(p_q, p_twh + lb + TW_ATT, p_twl + lb + TW_ATT,
                                        p_att, NQ, 96, 256, b_att + l*96, nullptr, 0,0,0);
        k_softmax12<<<(NQ*HEADS + 255)/256, 256>>>(p_att);
        k_sample<<<NQ, 256>>>(p_off, p_att, p_val, p_agg);
        tgemm<3><<<dim3(4, MBT), 256>>>(p_agg, p_twh + lb + TW_OUT, p_twl + lb + TW_OUT,
                                        p_qt, NQ, 256, 256, b_out + l*D, p_q, 0,0,0);
        k_ln<<<NQ, 256>>>(p_qt, p_q, ln1_g + l*D, ln1_b + l*D);
        tgemm<2><<<dim3(8, MBT), 256>>>(p_q, p_twh + lb + TW_FF1, p_twl + lb + TW_FF1,
                                        p_h1, NQ, 512, 256, b_ff1 + l*FFN, nullptr, 0,0,0);
        tgemm<3><<<dim3(4, MBT), 256>>>(p_h1, p_twh + lb + TW_FF2, p_twl + lb + TW_FF2,
                                        p_qt, NQ, 256, 512, b_ff2 + l*D, p_q, 0,0,0);
        k_ln<<<NQ, 256>>>(p_qt, p_q, ln2_g + l*D, ln2_b + l*D);
    }

    // deconv as 8 parity tensor GEMMs (scatter epilogue)
    for (int r = 0; r < 8; r++) {
        tgemm<5><<<dim3(4, MBT), 256>>>(p_q, p_dwh + (size_t)r*D*D, p_dwl + (size_t)r*D*D,
                                        p_x1, NQ, 256, 256, nullptr, nullptr,
                                        (r >> 2) & 1, (r >> 1) & 1, r & 1);
    }

    // group norm 1 stats (apply is fused into prep)
    {
        long glen = 16L * (long)SPAT;
        k_gn_zero<<<1, 32>>>(p_sum);
        k_gn_stats<<<dim3(16, 64), 256>>>(p_x1, p_sum, glen);
        k_gn_fin<<<1, 32>>>(p_sum, p_mi, glen);
    }

    // fused GN1 apply + relu + transpose + fp16 convert into padded plane
    k_prep_gn<<<dim3(2500, 4), 256>>>(p_x1, p_mi, gn1_g, gn1_b, p_xh);

    // conv3 via single-fp16 mma.sync
    k_conv3_v5<<<dim3(SX/2, SY/4), 512, CV_SMEM>>>(p_xh, p_wh, out);

    // group norm 2 + relu
    {
        long glen = 12L * (long)SPAT;
        k_gn_zero<<<1, 32>>>(p_sum);
        k_gn_stats<<<dim3(16, 64), 256>>>(out, p_sum, glen);
        k_gn_fin<<<1, 32>>>(p_sum, p_mi, glen);
        k_gn_apply<<<4096, 256>>>(out, p_mi, gn2_g, gn2_b, 12, (long)SPAT, (long)OC3*SPAT);
    }
}